// round 8
// baseline (speedup 1.0000x reference)
#include <cuda_runtime.h>
#include <cuda_fp16.h>
#include <cstdint>

// ============================================================================
// Fused attention block via mma.sync (HMMA). fp16 hi/lo split arithmetic:
//   3-term (q/k proj, scores), 2-term (v/out proj), 1-term (ctx).
// 128x256 block tiles (256 thr, 8 warps, 2x4 grid of 64x64 warp tiles),
// BK=32, 2-stage cp.async, persistent-CTA tile scheduler (grid = #SMs).
// B=4, S=2048, D=1024.
// ============================================================================

#define TOK 8192
#define DIM 1024
#define SEQ 2048
#define BATCH 4

static const long long OUT_ELEMS = (long long)TOK * DIM;
static const long long PATTN_ELEMS = (long long)BATCH * SEQ * SEQ;
static const long long TD = (long long)TOK * DIM;

// ---------------- device scratch ----------------
__device__ __half g_xhi[TOK * DIM], g_xlo[TOK * DIM];
__device__ __half g_wThi[3 * DIM * DIM], g_wTlo[3 * DIM * DIM]; // q,k,v ^T
__device__ __half g_wpThi[DIM * DIM], g_wpTlo[DIM * DIM];
__device__ __half g_qkvhi[3 * TOK * DIM];
__device__ __half g_qkvlo[2 * TOK * DIM];                 // lo only for q,k
__device__ __half g_vThi[TOK * DIM];                      // [B][DIM][SEQ]
__device__ __half g_phi[BATCH * SEQ * SEQ];
__device__ __half g_ctxhi[TOK * DIM];
__device__ float  g_scores_fb[BATCH * SEQ * SEQ];

// ---------------- PTX helpers ----------------
__device__ __forceinline__ uint32_t smem_u32_f(const void* p) {
    uint32_t a;
    asm("{ .reg .u64 t; cvta.to.shared.u64 t, %1; cvt.u32.u64 %0, t; }"
        : "=r"(a) : "l"(p));
    return a;
}
__device__ __forceinline__ void cp16(uint32_t dst, const void* src) {
    asm volatile("cp.async.cg.shared.global [%0], [%1], 16;" :: "r"(dst), "l"(src));
}
__device__ __forceinline__ void cp_commit() { asm volatile("cp.async.commit_group;"); }
template <int N>
__device__ __forceinline__ void cp_wait() {
    asm volatile("cp.async.wait_group %0;" :: "n"(N));
}
__device__ __forceinline__ void ldm_x4(uint32_t r[4], uint32_t addr) {
    asm volatile("ldmatrix.sync.aligned.m8n8.x4.shared.b16 {%0,%1,%2,%3}, [%4];"
                 : "=r"(r[0]), "=r"(r[1]), "=r"(r[2]), "=r"(r[3]) : "r"(addr));
}
__device__ __forceinline__ void mma16816(float c[4], const uint32_t a[4],
                                         const uint32_t b0, const uint32_t b1) {
    asm volatile(
        "mma.sync.aligned.m16n8k16.row.col.f32.f16.f16.f32 "
        "{%0,%1,%2,%3},{%4,%5,%6,%7},{%8,%9},{%0,%1,%2,%3};"
        : "+f"(c[0]), "+f"(c[1]), "+f"(c[2]), "+f"(c[3])
        : "r"(a[0]), "r"(a[1]), "r"(a[2]), "r"(a[3]), "r"(b0), "r"(b1));
}

// smem tiles, pitch 80B rows (conflict-free for ldmatrix)
#define PITCH 80u
#define A_TILE (128u * PITCH)            // 10240 B
#define B_TILE (256u * PITCH)            // 20480 B

// ============================================================================
// GEMM core for one 128x256 output tile.
// Terms: ah*bh [+ al*bh if ASPLIT] [+ ah*bl if BSPLIT].
// ============================================================================
template <bool ASPLIT, bool BSPLIT, bool WF32, bool HASBIAS, bool WLO>
__device__ __forceinline__ void gemm_core(
    const __half* __restrict__ Ah, const __half* __restrict__ Al,
    const __half* __restrict__ Bh, const __half* __restrict__ Bl,
    const float* __restrict__ bias,
    float* __restrict__ Cf, __half* __restrict__ Chi, __half* __restrict__ Clo,
    int N, int K, float alpha, int row0, int col0, long long cOff)
{
    constexpr uint32_t OF_AH = 0u;
    constexpr uint32_t OF_BH = A_TILE;
    constexpr uint32_t OF_AL = A_TILE + B_TILE;                         // if ASPLIT
    constexpr uint32_t OF_BL = OF_AL + (ASPLIT ? A_TILE : 0u);          // if BSPLIT
    constexpr uint32_t STG_SZ = A_TILE + B_TILE +
        (ASPLIT ? A_TILE : 0u) + (BSPLIT ? B_TILE : 0u);

    extern __shared__ char smem_raw[];
    const uint32_t base = smem_u32_f(smem_raw);
    const int tid = threadIdx.x;
    const int warp = tid >> 5, lane = tid & 31;

    // A: 512 16B chunks (2/thread). B: 1024 chunks (4/thread).
    long long aOff[2]; uint32_t dA[2];
#pragma unroll
    for (int j = 0; j < 2; j++) {
        int c = tid + j * 256;
        int r = c >> 2, q = c & 3;
        aOff[j] = (long long)(row0 + r) * K + q * 8;
        dA[j] = (uint32_t)r * PITCH + (uint32_t)q * 16u;
    }
    long long bOff[4]; uint32_t dB[4];
#pragma unroll
    for (int j = 0; j < 4; j++) {
        int c = tid + j * 256;
        int r = c >> 2, q = c & 3;
        bOff[j] = (long long)(col0 + r) * K + q * 8;
        dB[j] = (uint32_t)r * PITCH + (uint32_t)q * 16u;
    }

    const int m0 = (warp & 1) * 64, n0 = (warp >> 1) * 64;
    const uint32_t aLane = (uint32_t)(lane & 15) * PITCH + (uint32_t)(lane >> 4) * 16u;
    const uint32_t bLane = (uint32_t)((lane & 7) + ((lane >> 4) << 3)) * PITCH +
                           (uint32_t)((lane >> 3) & 1) * 16u;

    float acc[4][8][4];
#pragma unroll
    for (int i = 0; i < 4; i++)
#pragma unroll
        for (int j = 0; j < 8; j++)
#pragma unroll
            for (int e = 0; e < 4; e++) acc[i][j][e] = 0.f;

    const int nk = K >> 5;

    {   // prologue: stage 0
        uint32_t sb = base;
#pragma unroll
        for (int j = 0; j < 2; j++) {
            cp16(sb + OF_AH + dA[j], Ah + aOff[j]);
            if (ASPLIT) cp16(sb + OF_AL + dA[j], Al + aOff[j]);
        }
#pragma unroll
        for (int j = 0; j < 4; j++) {
            cp16(sb + OF_BH + dB[j], Bh + bOff[j]);
            if (BSPLIT) cp16(sb + OF_BL + dB[j], Bl + bOff[j]);
        }
        cp_commit();
    }

    for (int i = 0; i < nk; i++) {
        cp_wait<0>();
        __syncthreads();

        if (i + 1 < nk) {
            uint32_t sb = base + (uint32_t)((i + 1) & 1) * STG_SZ;
            long long k0 = (long long)(i + 1) * 32;
#pragma unroll
            for (int j = 0; j < 2; j++) {
                cp16(sb + OF_AH + dA[j], Ah + aOff[j] + k0);
                if (ASPLIT) cp16(sb + OF_AL + dA[j], Al + aOff[j] + k0);
            }
#pragma unroll
            for (int j = 0; j < 4; j++) {
                cp16(sb + OF_BH + dB[j], Bh + bOff[j] + k0);
                if (BSPLIT) cp16(sb + OF_BL + dB[j], Bl + bOff[j] + k0);
            }
            cp_commit();
        }

        const uint32_t sb = base + (uint32_t)(i & 1) * STG_SZ;
#pragma unroll
        for (int ks = 0; ks < 2; ks++) {
            const uint32_t kb = (uint32_t)ks * 32u;
            uint32_t ah[4][4], al[4][4], bh[4][4], bl[4][4];
#pragma unroll
            for (int mf = 0; mf < 4; mf++) {
                uint32_t ro = (uint32_t)(m0 + mf * 16) * PITCH + kb + aLane;
                ldm_x4(ah[mf], sb + OF_AH + ro);
                if (ASPLIT) ldm_x4(al[mf], sb + OF_AL + ro);
            }
#pragma unroll
            for (int q = 0; q < 4; q++) {
                uint32_t ro = (uint32_t)(n0 + q * 16) * PITCH + kb + bLane;
                ldm_x4(bh[q], sb + OF_BH + ro);
                if (BSPLIT) ldm_x4(bl[q], sb + OF_BL + ro);
            }
#pragma unroll
            for (int mf = 0; mf < 4; mf++)
#pragma unroll
                for (int nf = 0; nf < 8; nf++) {
                    const int q = nf >> 1, h = (nf & 1) * 2;
                    mma16816(acc[mf][nf], ah[mf], bh[q][h], bh[q][h + 1]);
                    if (ASPLIT) mma16816(acc[mf][nf], al[mf], bh[q][h], bh[q][h + 1]);
                    if (BSPLIT) mma16816(acc[mf][nf], ah[mf], bl[q][h], bl[q][h + 1]);
                }
        }
    }

    // ---- epilogue (register-only; cross-tile smem safety via caller sync) ----
    const int tg = lane >> 2, tl = lane & 3;
#pragma unroll
    for (int mf = 0; mf < 4; mf++) {
#pragma unroll
        for (int nf = 0; nf < 8; nf++) {
            const int col = col0 + n0 + nf * 8 + tl * 2;
            float b0 = 0.f, b1 = 0.f;
            if (HASBIAS) { b0 = __ldg(bias + col); b1 = __ldg(bias + col + 1); }
#pragma unroll
            for (int hrow = 0; hrow < 2; hrow++) {
                const int row = row0 + m0 + mf * 16 + tg + hrow * 8;
                float v0 = acc[mf][nf][hrow * 2 + 0] * alpha + b0;
                float v1 = acc[mf][nf][hrow * 2 + 1] * alpha + b1;
                const long long off = cOff + (long long)row * N + col;
                if (WF32) {
                    float2 o; o.x = v0; o.y = v1;
                    *(float2*)(Cf + off) = o;
                } else {
                    __half h0 = __float2half_rn(v0);
                    __half h1 = __float2half_rn(v1);
                    __half2 th; th.x = h0; th.y = h1;
                    *(__half2*)(Chi + off) = th;
                    if (WLO) {
                        __half2 tlh;
                        tlh.x = __float2half_rn(v0 - __half2float(h0));
                        tlh.y = __float2half_rn(v1 - __half2float(h1));
                        *(__half2*)(Clo + off) = tlh;
                    }
                }
            }
        }
    }
}

// ---------------- persistent GEMM: grid-stride over (ntz, nty, ntx) tiles ---
template <bool ASPLIT, bool BSPLIT, bool WF32, bool HASBIAS, bool WLO>
__global__ void __launch_bounds__(256) mma_gemm_p(
    const __half* __restrict__ Ah_g, const __half* __restrict__ Al_g,
    const __half* __restrict__ Bh_g, const __half* __restrict__ Bl_g,
    const float* __restrict__ bias,
    float* __restrict__ Cf, __half* __restrict__ Chi, __half* __restrict__ Clo,
    int N, int K, float alpha,
    long long sA, long long sB, long long sC,
    int ntx, int nty, int ntz)
{
    const int total = ntx * nty * ntz;
    const int nxy = ntx * nty;
    for (int t = blockIdx.x; t < total; t += gridDim.x) {
        const int tz = t / nxy;
        const int r = t - tz * nxy;
        const int ty = r / ntx;
        const int tx = r - ty * ntx;
        __syncthreads();   // previous tile's smem reads complete before refill
        gemm_core<ASPLIT, BSPLIT, WF32, HASBIAS, WLO>(
            Ah_g + (long long)tz * sA, ASPLIT ? (Al_g + (long long)tz * sA) : nullptr,
            Bh_g + (long long)tz * sB, BSPLIT ? (Bl_g + (long long)tz * sB) : nullptr,
            bias, Cf, Chi, Clo, N, K, alpha,
            ty * 128, tx * 256, (long long)tz * sC);
    }
}

// persistent fused q/k/v projection: z in {0:q,1:k} 3-term; {2:v} 2-term
__global__ void __launch_bounds__(256) qkv_gemm_p(
    const __half* __restrict__ xhi, const __half* __restrict__ xlo,
    const __half* __restrict__ wThi, const __half* __restrict__ wTlo,
    const float* __restrict__ bq, const float* __restrict__ bk,
    const float* __restrict__ bv,
    __half* __restrict__ outhi, __half* __restrict__ outlo,
    int ntx, int nty)
{
    const int nxy = ntx * nty;
    const int total = 3 * nxy;
    for (int t = blockIdx.x; t < total; t += gridDim.x) {
        const int tz = t / nxy;
        const int r = t - tz * nxy;
        const int ty = r / ntx;
        const int tx = r - ty * ntx;
        const long long wOff = (long long)tz * DIM * DIM;
        __syncthreads();
        if (tz == 2) {
            gemm_core<false, true, false, true, false>(
                xhi, nullptr, wThi + wOff, wTlo + wOff, bv,
                nullptr, outhi, nullptr, DIM, DIM, 1.f,
                ty * 128, tx * 256, 2 * TD);
        } else {
            const float* bias = (tz == 0) ? bq : bk;
            gemm_core<true, true, false, true, true>(
                xhi, xlo, wThi + wOff, wTlo + wOff, bias,
                nullptr, outhi, outlo, DIM, DIM, 1.f,
                ty * 128, tx * 256, (long long)tz * TD);
        }
    }
}

// smem budgets (2 stages each)
#define SMEM_3T (2 * (2 * 10240 + 2 * 20480))   // 122880
#define SMEM_2T (2 * (10240 + 2 * 20480))       // 102400
#define SMEM_1T (2 * (10240 + 20480))           // 61440

// ============================================================================
// helper kernels
// ============================================================================
__global__ void __launch_bounds__(256) convert_split_kernel(
    const float* __restrict__ in, __half* __restrict__ hi,
    __half* __restrict__ lo, long long n4)
{
    long long i = (long long)blockIdx.x * 256 + threadIdx.x;
    if (i >= n4) return;
    float4 v = ((const float4*)in)[i];
    __half h0 = __float2half_rn(v.x), h1 = __float2half_rn(v.y);
    __half h2 = __float2half_rn(v.z), h3 = __float2half_rn(v.w);
    __half2 a, b; a.x = h0; a.y = h1; b.x = h2; b.y = h3;
    ((__half2*)hi)[i * 2 + 0] = a;
    ((__half2*)hi)[i * 2 + 1] = b;
    __half2 c, d;
    c.x = __float2half_rn(v.x - __half2float(h0));
    c.y = __float2half_rn(v.y - __half2float(h1));
    d.x = __float2half_rn(v.z - __half2float(h2));
    d.y = __float2half_rn(v.w - __half2float(h3));
    ((__half2*)lo)[i * 2 + 0] = c;
    ((__half2*)lo)[i * 2 + 1] = d;
}

__global__ void __launch_bounds__(256) transpose_split_kernel(
    const float* __restrict__ in, __half* __restrict__ hi,
    __half* __restrict__ lo, int R, int C)
{
    __shared__ float t[32][33];
    const int c0 = blockIdx.x * 32, r0 = blockIdx.y * 32;
    const int tx = threadIdx.x & 31, ty = threadIdx.x >> 5;
#pragma unroll
    for (int j = 0; j < 4; j++)
        t[ty + j * 8][tx] = in[(long long)(r0 + ty + j * 8) * C + c0 + tx];
    __syncthreads();
#pragma unroll
    for (int j = 0; j < 4; j++) {
        int oc = c0 + ty + j * 8;
        float v = t[tx][ty + j * 8];
        long long o = (long long)oc * R + r0 + tx;
        __half h = __float2half_rn(v);
        hi[o] = h;
        lo[o] = __float2half_rn(v - __half2float(h));
    }
}

__global__ void __launch_bounds__(256) transpose_half_kernel(
    const __half* __restrict__ in, __half* __restrict__ outp,
    int R, int C, long long sIn, long long sOut)
{
    __shared__ __half t[32][34];
    const __half* src = in + (long long)blockIdx.z * sIn;
    const int c0 = blockIdx.x * 32, r0 = blockIdx.y * 32;
    const int tx = threadIdx.x & 31, ty = threadIdx.x >> 5;
#pragma unroll
    for (int j = 0; j < 4; j++)
        t[ty + j * 8][tx] = src[(long long)(r0 + ty + j * 8) * C + c0 + tx];
    __syncthreads();
#pragma unroll
    for (int j = 0; j < 4; j++) {
        int oc = c0 + ty + j * 8;
        long long o = (long long)blockIdx.z * sOut + (long long)oc * R + r0 + tx;
        outp[o] = t[tx][ty + j * 8];
    }
}

__global__ void __launch_bounds__(256) softmax2048_kernel(
    float* __restrict__ p, __half* __restrict__ phi)
{
    const long long roff = (long long)blockIdx.x * 2048;
    float* row = p + roff;
    const int tid = threadIdx.x;

    float4 v0 = ((const float4*)row)[tid];
    float4 v1 = ((const float4*)row)[tid + 256];

    float m = fmaxf(fmaxf(fmaxf(v0.x, v0.y), fmaxf(v0.z, v0.w)),
                    fmaxf(fmaxf(v1.x, v1.y), fmaxf(v1.z, v1.w)));
    __shared__ float red[8];
#pragma unroll
    for (int o = 16; o; o >>= 1) m = fmaxf(m, __shfl_xor_sync(0xffffffffu, m, o));
    if ((tid & 31) == 0) red[tid >> 5] = m;
    __syncthreads();
    m = red[0];
#pragma unroll
    for (int i = 1; i < 8; i++) m = fmaxf(m, red[i]);
    __syncthreads();

    v0.x = expf(v0.x - m); v0.y = expf(v0.y - m);
    v0.z = expf(v0.z - m); v0.w = expf(v0.w - m);
    v1.x = expf(v1.x - m); v1.y = expf(v1.y - m);
    v1.z = expf(v1.z - m); v1.w = expf(v1.w - m);

    float s = (v0.x + v0.y) + (v0.z + v0.w) + (v1.x + v1.y) + (v1.z + v1.w);
#pragma unroll
    for (int o = 16; o; o >>= 1) s += __shfl_xor_sync(0xffffffffu, s, o);
    if ((tid & 31) == 0) red[tid >> 5] = s;
    __syncthreads();
    s = ((red[0] + red[1]) + (red[2] + red[3])) +
        ((red[4] + red[5]) + (red[6] + red[7]));
    float inv = 1.0f / s;

    v0.x *= inv; v0.y *= inv; v0.z *= inv; v0.w *= inv;
    v1.x *= inv; v1.y *= inv; v1.z *= inv; v1.w *= inv;

    ((float4*)row)[tid] = v0;
    ((float4*)row)[tid + 256] = v1;

    const float vv[8] = {v0.x, v0.y, v0.z, v0.w, v1.x, v1.y, v1.z, v1.w};
    const long long off[2] = {roff + (long long)tid * 4,
                              roff + (long long)(tid + 256) * 4};
#pragma unroll
    for (int hseg = 0; hseg < 2; hseg++) {
#pragma unroll
        for (int g = 0; g < 2; g++) {
            __half2 th;
            th.x = __float2half_rn(vv[hseg * 4 + g * 2]);
            th.y = __float2half_rn(vv[hseg * 4 + g * 2 + 1]);
            *(__half2*)(phi + off[hseg] + g * 2) = th;
        }
    }
}

// ============================================================================
// host launcher
// ============================================================================
extern "C" void kernel_launch(void* const* d_in, const int* in_sizes, int n_in,
                              void* d_out, int out_size)
{
    const float* x  = (const float*)d_in[0];
    const float* wq = (const float*)d_in[1];
    const float* bq = (const float*)d_in[2];
    const float* wk = (const float*)d_in[3];
    const float* bk = (const float*)d_in[4];
    const float* wv = (const float*)d_in[5];
    const float* bv = (const float*)d_in[6];
    const float* wp = (const float*)d_in[7];
    const float* bp = (const float*)d_in[8];
    float* out = (float*)d_out;

#define SYM(p, s) void* p##_; cudaGetSymbolAddress(&p##_, s);
    SYM(xhi, g_xhi) SYM(xlo, g_xlo)
    SYM(wth, g_wThi) SYM(wtl, g_wTlo)
    SYM(wph, g_wpThi) SYM(wpl, g_wpTlo)
    SYM(qkvh, g_qkvhi) SYM(qkvl, g_qkvlo)
    SYM(vth, g_vThi)
    SYM(phi, g_phi)
    SYM(cxh, g_ctxhi)
    SYM(sfb, g_scores_fb)
#undef SYM
#define HF(p) ((__half*)p##_)

    float* pattn = (out_size >= (long long)(OUT_ELEMS + PATTN_ELEMS))
                       ? (out + OUT_ELEMS) : (float*)sfb_;

    static int nPersist = 0;
    if (nPersist == 0) {
        int nsm = 148;
        cudaDeviceGetAttribute(&nsm, cudaDevAttrMultiProcessorCount, 0);
        nPersist = nsm;
    }

    cudaFuncSetAttribute(qkv_gemm_p, cudaFuncAttributeMaxDynamicSharedMemorySize, SMEM_3T);
    cudaFuncSetAttribute(mma_gemm_p<true,  true,  true,  false, false>, cudaFuncAttributeMaxDynamicSharedMemorySize, SMEM_3T);
    cudaFuncSetAttribute(mma_gemm_p<false, false, false, false, false>, cudaFuncAttributeMaxDynamicSharedMemorySize, SMEM_1T);
    cudaFuncSetAttribute(mma_gemm_p<false, true,  true,  true,  false>, cudaFuncAttributeMaxDynamicSharedMemorySize, SMEM_2T);

    // 1) split x
    convert_split_kernel<<<(TOK * DIM / 4 + 255) / 256, 256>>>(
        x, HF(xhi), HF(xlo), TOK * DIM / 4);

    // 2) transpose + split weights
    dim3 gW(DIM / 32, DIM / 32, 1);
    transpose_split_kernel<<<gW, 256>>>(wq, HF(wth) + 0 * DIM * DIM, HF(wtl) + 0 * DIM * DIM, DIM, DIM);
    transpose_split_kernel<<<gW, 256>>>(wk, HF(wth) + 1 * DIM * DIM, HF(wtl) + 1 * DIM * DIM, DIM, DIM);
    transpose_split_kernel<<<gW, 256>>>(wv, HF(wth) + 2 * DIM * DIM, HF(wtl) + 2 * DIM * DIM, DIM, DIM);
    transpose_split_kernel<<<gW, 256>>>(wp, HF(wph), HF(wpl), DIM, DIM);

    // 3) fused q,k,v projections (persistent; 3*4*64 = 768 tiles)
    qkv_gemm_p<<<nPersist, 256, SMEM_3T>>>(
        HF(xhi), HF(xlo), HF(wth), HF(wtl), bq, bk, bv, HF(qkvh), HF(qkvl),
        DIM / 256, TOK / 128);

    const __half* qhi = HF(qkvh) + 0 * TD; const __half* qlo = HF(qkvl) + 0 * TD;
    const __half* khi = HF(qkvh) + 1 * TD; const __half* klo = HF(qkvl) + 1 * TD;
    const __half* vhi = HF(qkvh) + 2 * TD;

    // 4) transpose v (hi only) per batch -> vT[b][d][t]
    dim3 gVT(DIM / 32, SEQ / 32, BATCH);
    transpose_half_kernel<<<gVT, 256>>>(vhi, HF(vth), SEQ, DIM,
                                        (long long)SEQ * DIM, (long long)DIM * SEQ);

    // 5) scores = 32 * q @ k^T (3-term; 8*16*4 = 512 tiles)
    mma_gemm_p<true, true, true, false, false><<<nPersist, 256, SMEM_3T>>>(
        qhi, qlo, khi, klo, nullptr, pattn, nullptr, nullptr,
        SEQ, DIM, 32.f,
        (long long)SEQ * DIM, (long long)SEQ * DIM, (long long)SEQ * SEQ,
        SEQ / 256, SEQ / 128, BATCH);

    // 6) softmax in place + fp16 p_hi
    softmax2048_kernel<<<TOK, 256>>>(pattn, HF(phi));

    // 7) ctx = p_hi @ v_hi (1-term; 4*16*4 = 256 tiles)
    mma_gemm_p<false, false, false, false, false><<<nPersist, 256, SMEM_1T>>>(
        HF(phi), nullptr, HF(vth), nullptr, nullptr, nullptr, HF(cxh), nullptr,
        DIM, SEQ, 1.f,
        (long long)SEQ * SEQ, (long long)DIM * SEQ, (long long)SEQ * DIM,
        DIM / 256, SEQ / 128, BATCH);

    // 8) out = ctx_hi @ (wp_hi + wp_lo) + bp (2-term; 4*64 = 256 tiles)
    mma_gemm_p<false, true, true, true, false><<<nPersist, 256, SMEM_2T>>>(
        HF(cxh), nullptr, HF(wph), HF(wpl), bp, out, nullptr, nullptr,
        DIM, DIM, 1.f, 0, 0, 0,
        DIM / 256, TOK / 128, 1);
}

// round 9
// speedup vs baseline: 1.1197x; 1.1197x over previous
#include <cuda_runtime.h>
#include <cuda_fp16.h>
#include <cstdint>

// ============================================================================
// Fused attention block via mma.sync (HMMA). fp16 hi/lo split arithmetic:
//   3-term (q/k proj, scores), 2-term (v/out proj), 1-term (ctx).
// 128x128 block tiles, 128 thr / 4 warps, 64x64 warp tiles, 2 CTA/SM.
// Per-variant cp.async depth: 2-stage (3-term), 3-stage (2-term),
// 4-stage (1-term). Persistent-CTA tile scheduler (grid = 2*SMs).
// v-transpose fused into qkv epilogue (direct vT store).
// B=4, S=2048, D=1024.
// ============================================================================

#define TOK 8192
#define DIM 1024
#define SEQ 2048
#define BATCH 4

static const long long OUT_ELEMS = (long long)TOK * DIM;
static const long long PATTN_ELEMS = (long long)BATCH * SEQ * SEQ;
static const long long TD = (long long)TOK * DIM;

// ---------------- device scratch ----------------
__device__ __half g_xhi[TOK * DIM], g_xlo[TOK * DIM];
__device__ __half g_wThi[3 * DIM * DIM], g_wTlo[3 * DIM * DIM]; // q,k,v ^T
__device__ __half g_wpThi[DIM * DIM], g_wpTlo[DIM * DIM];
__device__ __half g_qkhi[2 * TOK * DIM], g_qklo[2 * TOK * DIM]; // q,k splits
__device__ __half g_vThi[TOK * DIM];                      // [B][DIM][SEQ]
__device__ __half g_phi[BATCH * SEQ * SEQ];
__device__ __half g_ctxhi[TOK * DIM];
__device__ float  g_scores_fb[BATCH * SEQ * SEQ];

// ---------------- PTX helpers ----------------
__device__ __forceinline__ uint32_t smem_u32_f(const void* p) {
    uint32_t a;
    asm("{ .reg .u64 t; cvta.to.shared.u64 t, %1; cvt.u32.u64 %0, t; }"
        : "=r"(a) : "l"(p));
    return a;
}
__device__ __forceinline__ void cp16(uint32_t dst, const void* src) {
    asm volatile("cp.async.cg.shared.global [%0], [%1], 16;" :: "r"(dst), "l"(src));
}
__device__ __forceinline__ void cp_commit() { asm volatile("cp.async.commit_group;"); }
template <int N>
__device__ __forceinline__ void cp_wait() {
    asm volatile("cp.async.wait_group %0;" :: "n"(N));
}
__device__ __forceinline__ void ldm_x4(uint32_t r[4], uint32_t addr) {
    asm volatile("ldmatrix.sync.aligned.m8n8.x4.shared.b16 {%0,%1,%2,%3}, [%4];"
                 : "=r"(r[0]), "=r"(r[1]), "=r"(r[2]), "=r"(r[3]) : "r"(addr));
}
__device__ __forceinline__ void mma16816(float c[4], const uint32_t a[4],
                                         const uint32_t b0, const uint32_t b1) {
    asm volatile(
        "mma.sync.aligned.m16n8k16.row.col.f32.f16.f16.f32 "
        "{%0,%1,%2,%3},{%4,%5,%6,%7},{%8,%9},{%0,%1,%2,%3};"
        : "+f"(c[0]), "+f"(c[1]), "+f"(c[2]), "+f"(c[3])
        : "r"(a[0]), "r"(a[1]), "r"(a[2]), "r"(a[3]), "r"(b0), "r"(b1));
}

// smem tile: 128 rows x 32 halfs, pitch 80B (conflict-free for ldmatrix)
#define PITCH 80u
#define TILE_B (128u * PITCH)            // 10240 B

// ============================================================================
// GEMM core for one 128x128 output tile.
// Terms: ah*bh [+ al*bh if ASPLIT] [+ ah*bl if BSPLIT]. NS = pipeline stages.
// WTRANS: write Chi transposed (vT[b][d][t]); cOff pre-adjusted by caller.
// ============================================================================
template <int NS, bool ASPLIT, bool BSPLIT, bool WF32, bool HASBIAS, bool WLO,
          bool WTRANS>
__device__ __forceinline__ void gemm_core(
    const __half* __restrict__ Ah, const __half* __restrict__ Al,
    const __half* __restrict__ Bh, const __half* __restrict__ Bl,
    const float* __restrict__ bias,
    float* __restrict__ Cf, __half* __restrict__ Chi, __half* __restrict__ Clo,
    int N, int K, float alpha, int row0, int col0, long long cOff)
{
    constexpr uint32_t OF_AH = 0u;
    constexpr uint32_t OF_BH = TILE_B;
    constexpr uint32_t OF_AL = 2u * TILE_B;
    constexpr uint32_t OF_BL = (ASPLIT ? 3u : 2u) * TILE_B;
    constexpr uint32_t STG_SZ = (2u + (ASPLIT ? 1u : 0u) + (BSPLIT ? 1u : 0u)) * TILE_B;

    extern __shared__ char smem_raw[];
    const uint32_t base = smem_u32_f(smem_raw);
    const int tid = threadIdx.x;
    const int warp = tid >> 5, lane = tid & 31;

    long long aOff[4], bOff[4];
    uint32_t dOff[4];
#pragma unroll
    for (int j = 0; j < 4; j++) {
        int c = tid + j * 128;
        int r = c >> 2, q = c & 3;
        aOff[j] = (long long)(row0 + r) * K + q * 8;
        bOff[j] = (long long)(col0 + r) * K + q * 8;
        dOff[j] = (uint32_t)r * PITCH + (uint32_t)q * 16u;
    }

    const int m0 = (warp & 1) * 64, n0 = (warp >> 1) * 64;
    const uint32_t aLane = (uint32_t)(lane & 15) * PITCH + (uint32_t)(lane >> 4) * 16u;
    const uint32_t bLane = (uint32_t)((lane & 7) + ((lane >> 4) << 3)) * PITCH +
                           (uint32_t)((lane >> 3) & 1) * 16u;

    float acc[4][8][4];
#pragma unroll
    for (int i = 0; i < 4; i++)
#pragma unroll
        for (int j = 0; j < 8; j++)
#pragma unroll
            for (int e = 0; e < 4; e++) acc[i][j][e] = 0.f;

    const int nk = K >> 5;

    // prologue: stages 0 .. NS-2
#pragma unroll
    for (int s = 0; s < NS - 1; s++) {
        uint32_t sb = base + (uint32_t)s * STG_SZ;
        long long k0 = (long long)s * 32;
#pragma unroll
        for (int j = 0; j < 4; j++) {
            cp16(sb + OF_AH + dOff[j], Ah + aOff[j] + k0);
            if (ASPLIT) cp16(sb + OF_AL + dOff[j], Al + aOff[j] + k0);
            cp16(sb + OF_BH + dOff[j], Bh + bOff[j] + k0);
            if (BSPLIT) cp16(sb + OF_BL + dOff[j], Bl + bOff[j] + k0);
        }
        cp_commit();
    }

    for (int i = 0; i < nk; i++) {
        // wait until stage i resident: pending groups > min(nk-1-i, NS-2) drain
        const int pend = (nk - 1 - i < NS - 2) ? (nk - 1 - i) : (NS - 2);
        if (pend >= 2)      cp_wait<2>();
        else if (pend == 1) cp_wait<1>();
        else                cp_wait<0>();
        __syncthreads();   // compute(i-1) done -> its buffer is refillable

        if (i + NS - 1 < nk) {
            const int s = (i + NS - 1) % NS;
            uint32_t sb = base + (uint32_t)s * STG_SZ;
            long long k0 = (long long)(i + NS - 1) * 32;
#pragma unroll
            for (int j = 0; j < 4; j++) {
                cp16(sb + OF_AH + dOff[j], Ah + aOff[j] + k0);
                if (ASPLIT) cp16(sb + OF_AL + dOff[j], Al + aOff[j] + k0);
                cp16(sb + OF_BH + dOff[j], Bh + bOff[j] + k0);
                if (BSPLIT) cp16(sb + OF_BL + dOff[j], Bl + bOff[j] + k0);
            }
            cp_commit();
        }

        const uint32_t sb = base + (uint32_t)(i % NS) * STG_SZ;
#pragma unroll
        for (int ks = 0; ks < 2; ks++) {
            const uint32_t kb = (uint32_t)ks * 32u;
            uint32_t ah[4][4], al[4][4], bh[4][4], bl[4][4];
#pragma unroll
            for (int mf = 0; mf < 4; mf++) {
                uint32_t ro = (uint32_t)(m0 + mf * 16) * PITCH + kb + aLane;
                ldm_x4(ah[mf], sb + OF_AH + ro);
                if (ASPLIT) ldm_x4(al[mf], sb + OF_AL + ro);
            }
#pragma unroll
            for (int q = 0; q < 4; q++) {
                uint32_t ro = (uint32_t)(n0 + q * 16) * PITCH + kb + bLane;
                ldm_x4(bh[q], sb + OF_BH + ro);
                if (BSPLIT) ldm_x4(bl[q], sb + OF_BL + ro);
            }
#pragma unroll
            for (int mf = 0; mf < 4; mf++)
#pragma unroll
                for (int nf = 0; nf < 8; nf++) {
                    const int q = nf >> 1, h = (nf & 1) * 2;
                    mma16816(acc[mf][nf], ah[mf], bh[q][h], bh[q][h + 1]);
                    if (ASPLIT) mma16816(acc[mf][nf], al[mf], bh[q][h], bh[q][h + 1]);
                    if (BSPLIT) mma16816(acc[mf][nf], ah[mf], bl[q][h], bl[q][h + 1]);
                }
        }
    }

    // ---- epilogue (register-only; cross-tile smem safety via caller sync) ----
    const int tg = lane >> 2, tl = lane & 3;
#pragma unroll
    for (int mf = 0; mf < 4; mf++) {
#pragma unroll
        for (int nf = 0; nf < 8; nf++) {
            const int col = col0 + n0 + nf * 8 + tl * 2;
            float b0 = 0.f, b1 = 0.f;
            if (HASBIAS) { b0 = __ldg(bias + col); b1 = __ldg(bias + col + 1); }
#pragma unroll
            for (int hrow = 0; hrow < 2; hrow++) {
                const int row = row0 + m0 + mf * 16 + tg + hrow * 8;
                float v0 = acc[mf][nf][hrow * 2 + 0] * alpha + b0;
                float v1 = acc[mf][nf][hrow * 2 + 1] * alpha + b1;
                if (WTRANS) {
                    // vT[b][col][t]: cOff = b*SEQ*(DIM-1); index = cOff+col*SEQ+row
                    Chi[cOff + (long long)col * SEQ + row] = __float2half_rn(v0);
                    Chi[cOff + (long long)(col + 1) * SEQ + row] = __float2half_rn(v1);
                } else {
                    const long long off = cOff + (long long)row * N + col;
                    if (WF32) {
                        float2 o; o.x = v0; o.y = v1;
                        *(float2*)(Cf + off) = o;
                    } else {
                        __half h0 = __float2half_rn(v0);
                        __half h1 = __float2half_rn(v1);
                        __half2 th; th.x = h0; th.y = h1;
                        *(__half2*)(Chi + off) = th;
                        if (WLO) {
                            __half2 tlh;
                            tlh.x = __float2half_rn(v0 - __half2float(h0));
                            tlh.y = __float2half_rn(v1 - __half2float(h1));
                            *(__half2*)(Clo + off) = tlh;
                        }
                    }
                }
            }
        }
    }
}

// ---------------- persistent GEMM: grid-stride over (ntz, nty, ntx) tiles ---
template <int NS, bool ASPLIT, bool BSPLIT, bool WF32, bool HASBIAS, bool WLO>
__global__ void __launch_bounds__(128) mma_gemm_p(
    const __half* __restrict__ Ah_g, const __half* __restrict__ Al_g,
    const __half* __restrict__ Bh_g, const __half* __restrict__ Bl_g,
    const float* __restrict__ bias,
    float* __restrict__ Cf, __half* __restrict__ Chi, __half* __restrict__ Clo,
    int N, int K, float alpha,
    long long sA, long long sB, long long sC,
    int ntx, int nty, int ntz)
{
    const int total = ntx * nty * ntz;
    const int nxy = ntx * nty;
    for (int t = blockIdx.x; t < total; t += gridDim.x) {
        const int tz = t / nxy;
        const int r = t - tz * nxy;
        const int ty = r / ntx;
        const int tx = r - ty * ntx;
        __syncthreads();   // previous tile's smem reads complete before refill
        gemm_core<NS, ASPLIT, BSPLIT, WF32, HASBIAS, WLO, false>(
            Ah_g + (long long)tz * sA, ASPLIT ? (Al_g + (long long)tz * sA) : nullptr,
            Bh_g + (long long)tz * sB, BSPLIT ? (Bl_g + (long long)tz * sB) : nullptr,
            bias, Cf, Chi, Clo, N, K, alpha,
            ty * 128, tx * 128, (long long)tz * sC);
    }
}

// persistent fused q/k/v projection:
//   z in {0:q,1:k}: 3-term, 2-stage, hi+lo outputs
//   z == 2 (v):     2-term, 3-stage, hi output written TRANSPOSED into vT
__global__ void __launch_bounds__(128) qkv_gemm_p(
    const __half* __restrict__ xhi, const __half* __restrict__ xlo,
    const __half* __restrict__ wThi, const __half* __restrict__ wTlo,
    const float* __restrict__ bq, const float* __restrict__ bk,
    const float* __restrict__ bv,
    __half* __restrict__ qkhi, __half* __restrict__ qklo,
    __half* __restrict__ vThi,
    int ntx, int nty)
{
    const int nxy = ntx * nty;
    const int total = 3 * nxy;
    for (int t = blockIdx.x; t < total; t += gridDim.x) {
        const int tz = t / nxy;
        const int r = t - tz * nxy;
        const int ty = r / ntx;
        const int tx = r - ty * ntx;
        const long long wOff = (long long)tz * DIM * DIM;
        __syncthreads();
        if (tz == 2) {
            const long long batch = (long long)((ty * 128) >> 11);
            gemm_core<3, false, true, false, true, false, true>(
                xhi, nullptr, wThi + wOff, wTlo + wOff, bv,
                nullptr, vThi, nullptr, DIM, DIM, 1.f,
                ty * 128, tx * 128, batch * SEQ * (DIM - 1));
        } else {
            const float* bias = (tz == 0) ? bq : bk;
            gemm_core<2, true, true, false, true, true, false>(
                xhi, xlo, wThi + wOff, wTlo + wOff, bias,
                nullptr, qkhi, qklo, DIM, DIM, 1.f,
                ty * 128, tx * 128, (long long)tz * TD);
        }
    }
}

// smem budgets
#define SMEM_QKV (3 * 3 * 10240)        // v branch: 3 stages x 30720 = 92160
#define SMEM_3T  (2 * 4 * 10240)        // 2 stages x 40960 = 81920
#define SMEM_2T  (3 * 3 * 10240)        // 3 stages x 30720 = 92160
#define SMEM_1T  (4 * 2 * 10240)        // 4 stages x 20480 = 81920

// ============================================================================
// helper kernels
// ============================================================================
__global__ void __launch_bounds__(256) convert_split_kernel(
    const float* __restrict__ in, __half* __restrict__ hi,
    __half* __restrict__ lo, long long n4)
{
    long long i = (long long)blockIdx.x * 256 + threadIdx.x;
    if (i >= n4) return;
    float4 v = ((const float4*)in)[i];
    __half h0 = __float2half_rn(v.x), h1 = __float2half_rn(v.y);
    __half h2 = __float2half_rn(v.z), h3 = __float2half_rn(v.w);
    __half2 a, b; a.x = h0; a.y = h1; b.x = h2; b.y = h3;
    ((__half2*)hi)[i * 2 + 0] = a;
    ((__half2*)hi)[i * 2 + 1] = b;
    __half2 c, d;
    c.x = __float2half_rn(v.x - __half2float(h0));
    c.y = __float2half_rn(v.y - __half2float(h1));
    d.x = __float2half_rn(v.z - __half2float(h2));
    d.y = __float2half_rn(v.w - __half2float(h3));
    ((__half2*)lo)[i * 2 + 0] = c;
    ((__half2*)lo)[i * 2 + 1] = d;
}

__global__ void __launch_bounds__(256) transpose_split_kernel(
    const float* __restrict__ in, __half* __restrict__ hi,
    __half* __restrict__ lo, int R, int C)
{
    __shared__ float t[32][33];
    const int c0 = blockIdx.x * 32, r0 = blockIdx.y * 32;
    const int tx = threadIdx.x & 31, ty = threadIdx.x >> 5;
#pragma unroll
    for (int j = 0; j < 4; j++)
        t[ty + j * 8][tx] = in[(long long)(r0 + ty + j * 8) * C + c0 + tx];
    __syncthreads();
#pragma unroll
    for (int j = 0; j < 4; j++) {
        int oc = c0 + ty + j * 8;
        float v = t[tx][ty + j * 8];
        long long o = (long long)oc * R + r0 + tx;
        __half h = __float2half_rn(v);
        hi[o] = h;
        lo[o] = __float2half_rn(v - __half2float(h));
    }
}

__global__ void __launch_bounds__(256) softmax2048_kernel(
    float* __restrict__ p, __half* __restrict__ phi)
{
    const long long roff = (long long)blockIdx.x * 2048;
    float* row = p + roff;
    const int tid = threadIdx.x;

    float4 v0 = ((const float4*)row)[tid];
    float4 v1 = ((const float4*)row)[tid + 256];

    float m = fmaxf(fmaxf(fmaxf(v0.x, v0.y), fmaxf(v0.z, v0.w)),
                    fmaxf(fmaxf(v1.x, v1.y), fmaxf(v1.z, v1.w)));
    __shared__ float red[8];
#pragma unroll
    for (int o = 16; o; o >>= 1) m = fmaxf(m, __shfl_xor_sync(0xffffffffu, m, o));
    if ((tid & 31) == 0) red[tid >> 5] = m;
    __syncthreads();
    m = red[0];
#pragma unroll
    for (int i = 1; i < 8; i++) m = fmaxf(m, red[i]);
    __syncthreads();

    v0.x = expf(v0.x - m); v0.y = expf(v0.y - m);
    v0.z = expf(v0.z - m); v0.w = expf(v0.w - m);
    v1.x = expf(v1.x - m); v1.y = expf(v1.y - m);
    v1.z = expf(v1.z - m); v1.w = expf(v1.w - m);

    float s = (v0.x + v0.y) + (v0.z + v0.w) + (v1.x + v1.y) + (v1.z + v1.w);
#pragma unroll
    for (int o = 16; o; o >>= 1) s += __shfl_xor_sync(0xffffffffu, s, o);
    if ((tid & 31) == 0) red[tid >> 5] = s;
    __syncthreads();
    s = ((red[0] + red[1]) + (red[2] + red[3])) +
        ((red[4] + red[5]) + (red[6] + red[7]));
    float inv = 1.0f / s;

    v0.x *= inv; v0.y *= inv; v0.z *= inv; v0.w *= inv;
    v1.x *= inv; v1.y *= inv; v1.z *= inv; v1.w *= inv;

    ((float4*)row)[tid] = v0;
    ((float4*)row)[tid + 256] = v1;

    const float vv[8] = {v0.x, v0.y, v0.z, v0.w, v1.x, v1.y, v1.z, v1.w};
    const long long off[2] = {roff + (long long)tid * 4,
                              roff + (long long)(tid + 256) * 4};
#pragma unroll
    for (int hseg = 0; hseg < 2; hseg++) {
#pragma unroll
        for (int g = 0; g < 2; g++) {
            __half2 th;
            th.x = __float2half_rn(vv[hseg * 4 + g * 2]);
            th.y = __float2half_rn(vv[hseg * 4 + g * 2 + 1]);
            *(__half2*)(phi + off[hseg] + g * 2) = th;
        }
    }
}

// ============================================================================
// host launcher
// ============================================================================
extern "C" void kernel_launch(void* const* d_in, const int* in_sizes, int n_in,
                              void* d_out, int out_size)
{
    const float* x  = (const float*)d_in[0];
    const float* wq = (const float*)d_in[1];
    const float* bq = (const float*)d_in[2];
    const float* wk = (const float*)d_in[3];
    const float* bk = (const float*)d_in[4];
    const float* wv = (const float*)d_in[5];
    const float* bv = (const float*)d_in[6];
    const float* wp = (const float*)d_in[7];
    const float* bp = (const float*)d_in[8];
    float* out = (float*)d_out;

#define SYM(p, s) void* p##_; cudaGetSymbolAddress(&p##_, s);
    SYM(xhi, g_xhi) SYM(xlo, g_xlo)
    SYM(wth, g_wThi) SYM(wtl, g_wTlo)
    SYM(wph, g_wpThi) SYM(wpl, g_wpTlo)
    SYM(qkh, g_qkhi) SYM(qkl, g_qklo)
    SYM(vth, g_vThi)
    SYM(phi, g_phi)
    SYM(cxh, g_ctxhi)
    SYM(sfb, g_scores_fb)
#undef SYM
#define HF(p) ((__half*)p##_)

    float* pattn = (out_size >= (long long)(OUT_ELEMS + PATTN_ELEMS))
                       ? (out + OUT_ELEMS) : (float*)sfb_;

    static int nPersist = 0;
    if (nPersist == 0) {
        int nsm = 148;
        cudaDeviceGetAttribute(&nsm, cudaDevAttrMultiProcessorCount, 0);
        nPersist = 2 * nsm;
    }

    cudaFuncSetAttribute(qkv_gemm_p, cudaFuncAttributeMaxDynamicSharedMemorySize, SMEM_QKV);
    cudaFuncSetAttribute(mma_gemm_p<2, true,  true,  true,  false, false>, cudaFuncAttributeMaxDynamicSharedMemorySize, SMEM_3T);
    cudaFuncSetAttribute(mma_gemm_p<4, false, false, false, false, false>, cudaFuncAttributeMaxDynamicSharedMemorySize, SMEM_1T);
    cudaFuncSetAttribute(mma_gemm_p<3, false, true,  true,  true,  false>, cudaFuncAttributeMaxDynamicSharedMemorySize, SMEM_2T);

    // 1) split x
    convert_split_kernel<<<(TOK * DIM / 4 + 255) / 256, 256>>>(
        x, HF(xhi), HF(xlo), TOK * DIM / 4);

    // 2) transpose + split weights
    dim3 gW(DIM / 32, DIM / 32, 1);
    transpose_split_kernel<<<gW, 256>>>(wq, HF(wth) + 0 * DIM * DIM, HF(wtl) + 0 * DIM * DIM, DIM, DIM);
    transpose_split_kernel<<<gW, 256>>>(wk, HF(wth) + 1 * DIM * DIM, HF(wtl) + 1 * DIM * DIM, DIM, DIM);
    transpose_split_kernel<<<gW, 256>>>(wv, HF(wth) + 2 * DIM * DIM, HF(wtl) + 2 * DIM * DIM, DIM, DIM);
    transpose_split_kernel<<<gW, 256>>>(wp, HF(wph), HF(wpl), DIM, DIM);

    // 3) fused q,k,v projections; v written directly transposed into vT
    qkv_gemm_p<<<nPersist, 128, SMEM_QKV>>>(
        HF(xhi), HF(xlo), HF(wth), HF(wtl), bq, bk, bv,
        HF(qkh), HF(qkl), HF(vth),
        DIM / 128, TOK / 128);

    const __half* qhi = HF(qkh) + 0 * TD; const __half* qlo = HF(qkl) + 0 * TD;
    const __half* khi = HF(qkh) + 1 * TD; const __half* klo = HF(qkl) + 1 * TD;

    // 4) scores = 32 * q @ k^T (3-term, 2-stage; 1024 tiles)
    mma_gemm_p<2, true, true, true, false, false><<<nPersist, 128, SMEM_3T>>>(
        qhi, qlo, khi, klo, nullptr, pattn, nullptr, nullptr,
        SEQ, DIM, 32.f,
        (long long)SEQ * DIM, (long long)SEQ * DIM, (long long)SEQ * SEQ,
        SEQ / 128, SEQ / 128, BATCH);

    // 5) softmax in place + fp16 p_hi
    softmax2048_kernel<<<TOK, 256>>>(pattn, HF(phi));

    // 6) ctx = p_hi @ v_hi (1-term, 4-stage; 512 tiles)
    mma_gemm_p<4, false, false, false, false, false><<<nPersist, 128, SMEM_1T>>>(
        HF(phi), nullptr, HF(vth), nullptr, nullptr, nullptr, HF(cxh), nullptr,
        DIM, SEQ, 1.f,
        (long long)SEQ * SEQ, (long long)DIM * SEQ, (long long)SEQ * DIM,
        DIM / 128, SEQ / 128, BATCH);

    // 7) out = ctx_hi @ (wp_hi + wp_lo) + bp (2-term, 3-stage; 512 tiles)
    mma_gemm_p<3, false, true, true, true, false><<<nPersist, 128, SMEM_2T>>>(
        HF(cxh), nullptr, HF(wph), HF(wpl), bp, out, nullptr, nullptr,
        DIM, DIM, 1.f, 0, 0, 0,
        DIM / 128, TOK / 128, 1);
}

// round 10
// speedup vs baseline: 1.2125x; 1.0828x over previous
#include <cuda_runtime.h>
#include <cuda_fp16.h>
#include <cstdint>

// ============================================================================
// Fused attention block via mma.sync (HMMA), fp16 hi/lo split arithmetic.
// ALGEBRAIC REWRITE: q/k projections eliminated.
//   scores = 32*(x Wq)(x Wk)^T = 32*( x(Wq Wk^T)x^T + a_i + b_j + c )
//   MT = Wk·Wq^T ; t = x·MT^T ; scores = t·x^T  (+ rank-1 bias corrections)
// Terms: 3-term (MT, t, scores), 2-term (v/out proj), 1-term (ctx).
// 128x128 tiles, 128 thr/4 warps, 64x64 warp tiles, 2 CTA/SM, per-variant
// cp.async depth, persistent-CTA scheduler. B=4, S=2048, D=1024.
// ============================================================================

#define TOK 8192
#define DIM 1024
#define SEQ 2048
#define BATCH 4

static const long long OUT_ELEMS = (long long)TOK * DIM;
static const long long PATTN_ELEMS = (long long)BATCH * SEQ * SEQ;
static const long long TD = (long long)TOK * DIM;

// ---------------- device scratch ----------------
__device__ __half g_xhi[TOK * DIM], g_xlo[TOK * DIM];
__device__ __half g_wqsh[DIM * DIM], g_wqsl[DIM * DIM];   // Wq straight split
__device__ __half g_wksh[DIM * DIM], g_wksl[DIM * DIM];   // Wk straight split
__device__ __half g_wvTh[DIM * DIM], g_wvTl[DIM * DIM];   // Wv^T split
__device__ __half g_wpTh[DIM * DIM], g_wpTl[DIM * DIM];   // Wp^T split
__device__ __half g_mth[DIM * DIM], g_mtl[DIM * DIM];     // MT = Wk Wq^T split
__device__ __half g_thi[TOK * DIM], g_tlo[TOK * DIM];     // t = x M split
__device__ __half g_vThi[TOK * DIM];                      // [B][DIM][SEQ]
__device__ __half g_phi[BATCH * SEQ * SEQ];
__device__ __half g_ctxhi[TOK * DIM];
__device__ float  g_u[DIM], g_w[DIM], g_c[1];
__device__ float  g_av[TOK], g_bv[TOK];
__device__ float  g_scores_fb[BATCH * SEQ * SEQ];

// ---------------- PTX helpers ----------------
__device__ __forceinline__ uint32_t smem_u32_f(const void* p) {
    uint32_t a;
    asm("{ .reg .u64 t; cvta.to.shared.u64 t, %1; cvt.u32.u64 %0, t; }"
        : "=r"(a) : "l"(p));
    return a;
}
__device__ __forceinline__ void cp16(uint32_t dst, const void* src) {
    asm volatile("cp.async.cg.shared.global [%0], [%1], 16;" :: "r"(dst), "l"(src));
}
__device__ __forceinline__ void cp_commit() { asm volatile("cp.async.commit_group;"); }
template <int N>
__device__ __forceinline__ void cp_wait() {
    asm volatile("cp.async.wait_group %0;" :: "n"(N));
}
__device__ __forceinline__ void ldm_x4(uint32_t r[4], uint32_t addr) {
    asm volatile("ldmatrix.sync.aligned.m8n8.x4.shared.b16 {%0,%1,%2,%3}, [%4];"
                 : "=r"(r[0]), "=r"(r[1]), "=r"(r[2]), "=r"(r[3]) : "r"(addr));
}
__device__ __forceinline__ void mma16816(float c[4], const uint32_t a[4],
                                         const uint32_t b0, const uint32_t b1) {
    asm volatile(
        "mma.sync.aligned.m16n8k16.row.col.f32.f16.f16.f32 "
        "{%0,%1,%2,%3},{%4,%5,%6,%7},{%8,%9},{%0,%1,%2,%3};"
        : "+f"(c[0]), "+f"(c[1]), "+f"(c[2]), "+f"(c[3])
        : "r"(a[0]), "r"(a[1]), "r"(a[2]), "r"(a[3]), "r"(b0), "r"(b1));
}

#define PITCH 80u
#define TILE_B (128u * PITCH)            // 10240 B

// ============================================================================
// GEMM core for one 128x128 output tile.
// Terms: ah*bh [+ al*bh if ASPLIT] [+ ah*bl if BSPLIT]. NS = pipeline stages.
// WTRANS: transposed Chi store (vT). SCB: score-bias epilogue (av/bv/c).
// ============================================================================
template <int NS, bool ASPLIT, bool BSPLIT, bool WF32, bool HASBIAS, bool WLO,
          bool WTRANS, bool SCB>
__device__ __forceinline__ void gemm_core(
    const __half* __restrict__ Ah, const __half* __restrict__ Al,
    const __half* __restrict__ Bh, const __half* __restrict__ Bl,
    const float* __restrict__ bias,
    float* __restrict__ Cf, __half* __restrict__ Chi, __half* __restrict__ Clo,
    int N, int K, float alpha, int row0, int col0, long long cOff,
    const float* __restrict__ av, const float* __restrict__ bv,
    const float* __restrict__ cb)
{
    constexpr uint32_t OF_AH = 0u;
    constexpr uint32_t OF_BH = TILE_B;
    constexpr uint32_t OF_AL = 2u * TILE_B;
    constexpr uint32_t OF_BL = (ASPLIT ? 3u : 2u) * TILE_B;
    constexpr uint32_t STG_SZ = (2u + (ASPLIT ? 1u : 0u) + (BSPLIT ? 1u : 0u)) * TILE_B;

    extern __shared__ char smem_raw[];
    const uint32_t base = smem_u32_f(smem_raw);
    const int tid = threadIdx.x;
    const int warp = tid >> 5, lane = tid & 31;

    long long aOff[4], bOff[4];
    uint32_t dOff[4];
#pragma unroll
    for (int j = 0; j < 4; j++) {
        int c = tid + j * 128;
        int r = c >> 2, q = c & 3;
        aOff[j] = (long long)(row0 + r) * K + q * 8;
        bOff[j] = (long long)(col0 + r) * K + q * 8;
        dOff[j] = (uint32_t)r * PITCH + (uint32_t)q * 16u;
    }

    const int m0 = (warp & 1) * 64, n0 = (warp >> 1) * 64;
    const uint32_t aLane = (uint32_t)(lane & 15) * PITCH + (uint32_t)(lane >> 4) * 16u;
    const uint32_t bLane = (uint32_t)((lane & 7) + ((lane >> 4) << 3)) * PITCH +
                           (uint32_t)((lane >> 3) & 1) * 16u;

    float acc[4][8][4];
#pragma unroll
    for (int i = 0; i < 4; i++)
#pragma unroll
        for (int j = 0; j < 8; j++)
#pragma unroll
            for (int e = 0; e < 4; e++) acc[i][j][e] = 0.f;

    const int nk = K >> 5;

#pragma unroll
    for (int s = 0; s < NS - 1; s++) {
        uint32_t sb = base + (uint32_t)s * STG_SZ;
        long long k0 = (long long)s * 32;
#pragma unroll
        for (int j = 0; j < 4; j++) {
            cp16(sb + OF_AH + dOff[j], Ah + aOff[j] + k0);
            if (ASPLIT) cp16(sb + OF_AL + dOff[j], Al + aOff[j] + k0);
            cp16(sb + OF_BH + dOff[j], Bh + bOff[j] + k0);
            if (BSPLIT) cp16(sb + OF_BL + dOff[j], Bl + bOff[j] + k0);
        }
        cp_commit();
    }

    for (int i = 0; i < nk; i++) {
        const int pend = (nk - 1 - i < NS - 2) ? (nk - 1 - i) : (NS - 2);
        if (pend >= 2)      cp_wait<2>();
        else if (pend == 1) cp_wait<1>();
        else                cp_wait<0>();
        __syncthreads();

        if (i + NS - 1 < nk) {
            const int s = (i + NS - 1) % NS;
            uint32_t sb = base + (uint32_t)s * STG_SZ;
            long long k0 = (long long)(i + NS - 1) * 32;
#pragma unroll
            for (int j = 0; j < 4; j++) {
                cp16(sb + OF_AH + dOff[j], Ah + aOff[j] + k0);
                if (ASPLIT) cp16(sb + OF_AL + dOff[j], Al + aOff[j] + k0);
                cp16(sb + OF_BH + dOff[j], Bh + bOff[j] + k0);
                if (BSPLIT) cp16(sb + OF_BL + dOff[j], Bl + bOff[j] + k0);
            }
            cp_commit();
        }

        const uint32_t sb = base + (uint32_t)(i % NS) * STG_SZ;
#pragma unroll
        for (int ks = 0; ks < 2; ks++) {
            const uint32_t kb = (uint32_t)ks * 32u;
            uint32_t ah[4][4], al[4][4], bh[4][4], bl[4][4];
#pragma unroll
            for (int mf = 0; mf < 4; mf++) {
                uint32_t ro = (uint32_t)(m0 + mf * 16) * PITCH + kb + aLane;
                ldm_x4(ah[mf], sb + OF_AH + ro);
                if (ASPLIT) ldm_x4(al[mf], sb + OF_AL + ro);
            }
#pragma unroll
            for (int q = 0; q < 4; q++) {
                uint32_t ro = (uint32_t)(n0 + q * 16) * PITCH + kb + bLane;
                ldm_x4(bh[q], sb + OF_BH + ro);
                if (BSPLIT) ldm_x4(bl[q], sb + OF_BL + ro);
            }
#pragma unroll
            for (int mf = 0; mf < 4; mf++)
#pragma unroll
                for (int nf = 0; nf < 8; nf++) {
                    const int q = nf >> 1, h = (nf & 1) * 2;
                    mma16816(acc[mf][nf], ah[mf], bh[q][h], bh[q][h + 1]);
                    if (ASPLIT) mma16816(acc[mf][nf], al[mf], bh[q][h], bh[q][h + 1]);
                    if (BSPLIT) mma16816(acc[mf][nf], ah[mf], bl[q][h], bl[q][h + 1]);
                }
        }
    }

    // ---- epilogue ----
    const int tg = lane >> 2, tl = lane & 3;
    const float c0 = SCB ? __ldg(cb) : 0.f;
#pragma unroll
    for (int mf = 0; mf < 4; mf++) {
#pragma unroll
        for (int nf = 0; nf < 8; nf++) {
            const int col = col0 + n0 + nf * 8 + tl * 2;
            float b0 = 0.f, b1 = 0.f;
            if (HASBIAS) { b0 = __ldg(bias + col); b1 = __ldg(bias + col + 1); }
            float bc0 = 0.f, bc1 = 0.f;
            if (SCB) { bc0 = __ldg(bv + col) + c0; bc1 = __ldg(bv + col + 1) + c0; }
#pragma unroll
            for (int hrow = 0; hrow < 2; hrow++) {
                const int row = row0 + m0 + mf * 16 + tg + hrow * 8;
                float v0, v1;
                if (SCB) {
                    const float ar = __ldg(av + row);
                    v0 = (acc[mf][nf][hrow * 2 + 0] + ar + bc0) * alpha;
                    v1 = (acc[mf][nf][hrow * 2 + 1] + ar + bc1) * alpha;
                } else {
                    v0 = acc[mf][nf][hrow * 2 + 0] * alpha + b0;
                    v1 = acc[mf][nf][hrow * 2 + 1] * alpha + b1;
                }
                if (WTRANS) {
                    Chi[cOff + (long long)col * SEQ + row] = __float2half_rn(v0);
                    Chi[cOff + (long long)(col + 1) * SEQ + row] = __float2half_rn(v1);
                } else {
                    const long long off = cOff + (long long)row * N + col;
                    if (WF32) {
                        float2 o; o.x = v0; o.y = v1;
                        *(float2*)(Cf + off) = o;
                    } else {
                        __half h0 = __float2half_rn(v0);
                        __half h1 = __float2half_rn(v1);
                        __half2 th; th.x = h0; th.y = h1;
                        *(__half2*)(Chi + off) = th;
                        if (WLO) {
                            __half2 tlh;
                            tlh.x = __float2half_rn(v0 - __half2float(h0));
                            tlh.y = __float2half_rn(v1 - __half2float(h1));
                            *(__half2*)(Clo + off) = tlh;
                        }
                    }
                }
            }
        }
    }
}

// ---------------- persistent GEMM over (ntz, nty, ntx) tiles ----------------
template <int NS, bool ASPLIT, bool BSPLIT, bool WF32, bool HASBIAS, bool WLO,
          bool SCB>
__global__ void __launch_bounds__(128) mma_gemm_p(
    const __half* __restrict__ Ah_g, const __half* __restrict__ Al_g,
    const __half* __restrict__ Bh_g, const __half* __restrict__ Bl_g,
    const float* __restrict__ bias,
    float* __restrict__ Cf, __half* __restrict__ Chi, __half* __restrict__ Clo,
    int N, int K, float alpha,
    long long sA, long long sB, long long sC,
    int ntx, int nty, int ntz,
    const float* __restrict__ av, const float* __restrict__ bv,
    const float* __restrict__ cb)
{
    const int total = ntx * nty * ntz;
    const int nxy = ntx * nty;
    for (int t = blockIdx.x; t < total; t += gridDim.x) {
        const int tz = t / nxy;
        const int r = t - tz * nxy;
        const int ty = r / ntx;
        const int tx = r - ty * ntx;
        __syncthreads();
        gemm_core<NS, ASPLIT, BSPLIT, WF32, HASBIAS, WLO, false, SCB>(
            Ah_g + (long long)tz * sA, ASPLIT ? (Al_g + (long long)tz * sA) : nullptr,
            Bh_g + (long long)tz * sB, BSPLIT ? (Bl_g + (long long)tz * sB) : nullptr,
            bias, Cf, Chi, Clo, N, K, alpha,
            ty * 128, tx * 128, (long long)tz * sC,
            SCB ? (av + (long long)tz * SEQ) : nullptr,
            SCB ? (bv + (long long)tz * SEQ) : nullptr, cb);
    }
}

// persistent fused t/v kernel:
//   z==0: t = x @ MT^T (3-term, 2-stage, hi+lo out)
//   z==1: v = x @ Wv (2-term, 3-stage, transposed hi out into vT)
__global__ void __launch_bounds__(128) tv_gemm_p(
    const __half* __restrict__ xhi, const __half* __restrict__ xlo,
    const __half* __restrict__ mth, const __half* __restrict__ mtl,
    const __half* __restrict__ wvTh, const __half* __restrict__ wvTl,
    const float* __restrict__ bvb,
    __half* __restrict__ thi, __half* __restrict__ tlo,
    __half* __restrict__ vThi,
    int ntx, int nty)
{
    const int nxy = ntx * nty;
    const int total = 2 * nxy;
    for (int t = blockIdx.x; t < total; t += gridDim.x) {
        const int tz = t / nxy;
        const int r = t - tz * nxy;
        const int ty = r / ntx;
        const int tx = r - ty * ntx;
        __syncthreads();
        if (tz == 0) {
            gemm_core<2, true, true, false, false, true, false, false>(
                xhi, xlo, mth, mtl, nullptr,
                nullptr, thi, tlo, DIM, DIM, 1.f,
                ty * 128, tx * 128, 0, nullptr, nullptr, nullptr);
        } else {
            const long long batch = (long long)((ty * 128) >> 11);
            gemm_core<3, false, true, false, true, false, true, false>(
                xhi, nullptr, wvTh, wvTl, bvb,
                nullptr, vThi, nullptr, DIM, DIM, 1.f,
                ty * 128, tx * 128, batch * SEQ * (DIM - 1),
                nullptr, nullptr, nullptr);
        }
    }
}

// smem budgets
#define SMEM_TV  (3 * 3 * 10240)        // 92160 (v branch dominates)
#define SMEM_3T  (2 * 4 * 10240)        // 81920
#define SMEM_2T  (3 * 3 * 10240)        // 92160
#define SMEM_1T  (4 * 2 * 10240)        // 81920

// ============================================================================
// helper kernels
// ============================================================================
__global__ void __launch_bounds__(256) convert_split_kernel(
    const float* __restrict__ in, __half* __restrict__ hi,
    __half* __restrict__ lo, long long n4)
{
    long long i = (long long)blockIdx.x * 256 + threadIdx.x;
    if (i >= n4) return;
    float4 v = ((const float4*)in)[i];
    __half h0 = __float2half_rn(v.x), h1 = __float2half_rn(v.y);
    __half h2 = __float2half_rn(v.z), h3 = __float2half_rn(v.w);
    __half2 a, b; a.x = h0; a.y = h1; b.x = h2; b.y = h3;
    ((__half2*)hi)[i * 2 + 0] = a;
    ((__half2*)hi)[i * 2 + 1] = b;
    __half2 c, d;
    c.x = __float2half_rn(v.x - __half2float(h0));
    c.y = __float2half_rn(v.y - __half2float(h1));
    d.x = __float2half_rn(v.z - __half2float(h2));
    d.y = __float2half_rn(v.w - __half2float(h3));
    ((__half2*)lo)[i * 2 + 0] = c;
    ((__half2*)lo)[i * 2 + 1] = d;
}

__global__ void __launch_bounds__(256) transpose_split_kernel(
    const float* __restrict__ in, __half* __restrict__ hi,
    __half* __restrict__ lo, int R, int C)
{
    __shared__ float t[32][33];
    const int c0 = blockIdx.x * 32, r0 = blockIdx.y * 32;
    const int tx = threadIdx.x & 31, ty = threadIdx.x >> 5;
#pragma unroll
    for (int j = 0; j < 4; j++)
        t[ty + j * 8][tx] = in[(long long)(r0 + ty + j * 8) * C + c0 + tx];
    __syncthreads();
#pragma unroll
    for (int j = 0; j < 4; j++) {
        int oc = c0 + ty + j * 8;
        float v = t[tx][ty + j * 8];
        long long o = (long long)oc * R + r0 + tx;
        __half h = __float2half_rn(v);
        hi[o] = h;
        lo[o] = __float2half_rn(v - __half2float(h));
    }
}

// u = Wq*bk, w = Wk*bq (per output row), c = bq.bk
__global__ void __launch_bounds__(256) uvw_kernel(
    const float* __restrict__ wq, const float* __restrict__ wk,
    const float* __restrict__ bq, const float* __restrict__ bk,
    float* __restrict__ u, float* __restrict__ w, float* __restrict__ cb)
{
    const int d = blockIdx.x;
    const int tid = threadIdx.x;
    float su = 0.f, sw = 0.f;
    for (int f = tid; f < DIM; f += 256) {
        su += wq[(long long)d * DIM + f] * bk[f];
        sw += wk[(long long)d * DIM + f] * bq[f];
    }
    __shared__ float r1[256], r2[256];
    r1[tid] = su; r2[tid] = sw;
    __syncthreads();
    for (int s = 128; s; s >>= 1) {
        if (tid < s) { r1[tid] += r1[tid + s]; r2[tid] += r2[tid + s]; }
        __syncthreads();
    }
    if (tid == 0) { u[d] = r1[0]; w[d] = r2[0]; }
    if (d == 0 && tid == 0) {
        float c = 0.f;
        for (int f = 0; f < DIM; f++) c += bq[f] * bk[f];
        cb[0] = c;
    }
}

// av[i] = x_i . u ; bv[i] = x_i . w
__global__ void __launch_bounds__(256) av_kernel(
    const float* __restrict__ x, const float* __restrict__ u,
    const float* __restrict__ w, float* __restrict__ av, float* __restrict__ bv)
{
    const long long i = blockIdx.x;
    const float* xr = x + i * DIM;
    const int tid = threadIdx.x;
    float sa = 0.f, sb = 0.f;
    for (int d = tid; d < DIM; d += 256) {
        float xv = xr[d];
        sa += xv * u[d];
        sb += xv * w[d];
    }
    __shared__ float r1[256], r2[256];
    r1[tid] = sa; r2[tid] = sb;
    __syncthreads();
    for (int s = 128; s; s >>= 1) {
        if (tid < s) { r1[tid] += r1[tid + s]; r2[tid] += r2[tid + s]; }
        __syncthreads();
    }
    if (tid == 0) { av[i] = r1[0]; bv[i] = r2[0]; }
}

__global__ void __launch_bounds__(256) softmax2048_kernel(
    float* __restrict__ p, __half* __restrict__ phi)
{
    const long long roff = (long long)blockIdx.x * 2048;
    float* row = p + roff;
    const int tid = threadIdx.x;

    float4 v0 = ((const float4*)row)[tid];
    float4 v1 = ((const float4*)row)[tid + 256];

    float m = fmaxf(fmaxf(fmaxf(v0.x, v0.y), fmaxf(v0.z, v0.w)),
                    fmaxf(fmaxf(v1.x, v1.y), fmaxf(v1.z, v1.w)));
    __shared__ float red[8];
#pragma unroll
    for (int o = 16; o; o >>= 1) m = fmaxf(m, __shfl_xor_sync(0xffffffffu, m, o));
    if ((tid & 31) == 0) red[tid >> 5] = m;
    __syncthreads();
    m = red[0];
#pragma unroll
    for (int i = 1; i < 8; i++) m = fmaxf(m, red[i]);
    __syncthreads();

    v0.x = expf(v0.x - m); v0.y = expf(v0.y - m);
    v0.z = expf(v0.z - m); v0.w = expf(v0.w - m);
    v1.x = expf(v1.x - m); v1.y = expf(v1.y - m);
    v1.z = expf(v1.z - m); v1.w = expf(v1.w - m);

    float s = (v0.x + v0.y) + (v0.z + v0.w) + (v1.x + v1.y) + (v1.z + v1.w);
#pragma unroll
    for (int o = 16; o; o >>= 1) s += __shfl_xor_sync(0xffffffffu, s, o);
    if ((tid & 31) == 0) red[tid >> 5] = s;
    __syncthreads();
    s = ((red[0] + red[1]) + (red[2] + red[3])) +
        ((red[4] + red[5]) + (red[6] + red[7]));
    float inv = 1.0f / s;

    v0.x *= inv; v0.y *= inv; v0.z *= inv; v0.w *= inv;
    v1.x *= inv; v1.y *= inv; v1.z *= inv; v1.w *= inv;

    ((float4*)row)[tid] = v0;
    ((float4*)row)[tid + 256] = v1;

    const float vv[8] = {v0.x, v0.y, v0.z, v0.w, v1.x, v1.y, v1.z, v1.w};
    const long long off[2] = {roff + (long long)tid * 4,
                              roff + (long long)(tid + 256) * 4};
#pragma unroll
    for (int hseg = 0; hseg < 2; hseg++) {
#pragma unroll
        for (int g = 0; g < 2; g++) {
            __half2 th;
            th.x = __float2half_rn(vv[hseg * 4 + g * 2]);
            th.y = __float2half_rn(vv[hseg * 4 + g * 2 + 1]);
            *(__half2*)(phi + off[hseg] + g * 2) = th;
        }
    }
}

// ============================================================================
// host launcher
// ============================================================================
extern "C" void kernel_launch(void* const* d_in, const int* in_sizes, int n_in,
                              void* d_out, int out_size)
{
    const float* x  = (const float*)d_in[0];
    const float* wq = (const float*)d_in[1];
    const float* bq = (const float*)d_in[2];
    const float* wk = (const float*)d_in[3];
    const float* bk = (const float*)d_in[4];
    const float* wv = (const float*)d_in[5];
    const float* bv = (const float*)d_in[6];
    const float* wp = (const float*)d_in[7];
    const float* bp = (const float*)d_in[8];
    float* out = (float*)d_out;

#define SYM(p, s) void* p##_; cudaGetSymbolAddress(&p##_, s);
    SYM(xhi, g_xhi) SYM(xlo, g_xlo)
    SYM(wqsh, g_wqsh) SYM(wqsl, g_wqsl)
    SYM(wksh, g_wksh) SYM(wksl, g_wksl)
    SYM(wvth, g_wvTh) SYM(wvtl, g_wvTl)
    SYM(wpth, g_wpTh) SYM(wptl, g_wpTl)
    SYM(mth, g_mth) SYM(mtl, g_mtl)
    SYM(thi, g_thi) SYM(tlo, g_tlo)
    SYM(vth, g_vThi)
    SYM(phi, g_phi)
    SYM(cxh, g_ctxhi)
    SYM(uu, g_u) SYM(ww, g_w) SYM(cc, g_c)
    SYM(avv, g_av) SYM(bvv, g_bv)
    SYM(sfb, g_scores_fb)
#undef SYM
#define HF(p) ((__half*)p##_)

    float* pattn = (out_size >= (long long)(OUT_ELEMS + PATTN_ELEMS))
                       ? (out + OUT_ELEMS) : (float*)sfb_;

    static int nPersist = 0;
    if (nPersist == 0) {
        int nsm = 148;
        cudaDeviceGetAttribute(&nsm, cudaDevAttrMultiProcessorCount, 0);
        nPersist = 2 * nsm;
    }

    cudaFuncSetAttribute(tv_gemm_p, cudaFuncAttributeMaxDynamicSharedMemorySize, SMEM_TV);
    cudaFuncSetAttribute(mma_gemm_p<2, true,  true,  false, false, true,  false>, cudaFuncAttributeMaxDynamicSharedMemorySize, SMEM_3T);
    cudaFuncSetAttribute(mma_gemm_p<2, true,  true,  true,  false, false, true >, cudaFuncAttributeMaxDynamicSharedMemorySize, SMEM_3T);
    cudaFuncSetAttribute(mma_gemm_p<4, false, false, false, false, false, false>, cudaFuncAttributeMaxDynamicSharedMemorySize, SMEM_1T);
    cudaFuncSetAttribute(mma_gemm_p<3, false, true,  true,  true,  false, false>, cudaFuncAttributeMaxDynamicSharedMemorySize, SMEM_2T);

    // 1) splits: x, Wq (straight), Wk (straight)
    convert_split_kernel<<<(TOK * DIM / 4 + 255) / 256, 256>>>(
        x, HF(xhi), HF(xlo), TOK * DIM / 4);
    convert_split_kernel<<<(DIM * DIM / 4 + 255) / 256, 256>>>(
        wq, HF(wqsh), HF(wqsl), DIM * DIM / 4);
    convert_split_kernel<<<(DIM * DIM / 4 + 255) / 256, 256>>>(
        wk, HF(wksh), HF(wksl), DIM * DIM / 4);

    // 2) transposed splits: Wv, Wp
    dim3 gW(DIM / 32, DIM / 32, 1);
    transpose_split_kernel<<<gW, 256>>>(wv, HF(wvth), HF(wvtl), DIM, DIM);
    transpose_split_kernel<<<gW, 256>>>(wp, HF(wpth), HF(wptl), DIM, DIM);

    // 3) bias correction vectors: u = Wq bk, w = Wk bq, c = bq.bk ;
    //    av = x.u, bv = x.w
    uvw_kernel<<<DIM, 256>>>(wq, wk, bq, bk, (float*)uu_, (float*)ww_, (float*)cc_);
    av_kernel<<<TOK, 256>>>(x, (float*)uu_, (float*)ww_, (float*)avv_, (float*)bvv_);

    // 4) MT = Wk @ Wq^T (3-term, hi/lo out; 64 tiles)
    mma_gemm_p<2, true, true, false, false, true, false><<<64, 128, SMEM_3T>>>(
        HF(wksh), HF(wksl), HF(wqsh), HF(wqsl), nullptr,
        nullptr, HF(mth), HF(mtl), DIM, DIM, 1.f, 0, 0, 0,
        DIM / 128, DIM / 128, 1, nullptr, nullptr, nullptr);

    // 5) fused t = x@MT^T (3-term) and v = x@Wv (2-term, transposed out)
    tv_gemm_p<<<nPersist, 128, SMEM_TV>>>(
        HF(xhi), HF(xlo), HF(mth), HF(mtl), HF(wvth), HF(wvtl), bv,
        HF(thi), HF(tlo), HF(vth), DIM / 128, TOK / 128);

    // 6) scores = 32*(t @ x^T + a_i + b_j + c) per batch (3-term, SCB epilogue)
    mma_gemm_p<2, true, true, true, false, false, true><<<nPersist, 128, SMEM_3T>>>(
        HF(thi), HF(tlo), HF(xhi), HF(xlo), nullptr, pattn, nullptr, nullptr,
        SEQ, DIM, 32.f,
        (long long)SEQ * DIM, (long long)SEQ * DIM, (long long)SEQ * SEQ,
        SEQ / 128, SEQ / 128, BATCH,
        (const float*)avv_, (const float*)bvv_, (const float*)cc_);

    // 7) softmax in place + fp16 p_hi
    softmax2048_kernel<<<TOK, 256>>>(pattn, HF(phi));

    // 8) ctx = p_hi @ v_hi (1-term, 4-stage)
    mma_gemm_p<4, false, false, false, false, false, false><<<nPersist, 128, SMEM_1T>>>(
        HF(phi), nullptr, HF(vth), nullptr, nullptr, nullptr, HF(cxh), nullptr,
        DIM, SEQ, 1.f,
        (long long)SEQ * SEQ, (long long)DIM * SEQ, (long long)SEQ * DIM,
        DIM / 128, SEQ / 128, BATCH, nullptr, nullptr, nullptr);

    // 9) out = ctx_hi @ (wp_hi + wp_lo) + bp (2-term, 3-stage)
    mma_gemm_p<3, false, true, true, true, false, false><<<nPersist, 128, SMEM_2T>>>(
        HF(cxh), nullptr, HF(wpth), HF(wptl), bp, out, nullptr, nullptr,
        DIM, DIM, 1.f, 0, 0, 0,
        DIM / 128, TOK / 128, 1, nullptr, nullptr, nullptr);
}

// round 11
// speedup vs baseline: 1.2453x; 1.0271x over previous
#include <cuda_runtime.h>
#include <cuda_fp16.h>
#include <cstdint>

// ============================================================================
// Fused attention block via mma.sync (HMMA), fp16 hi/lo split arithmetic.
// Algebraic rewrite: scores = 32*( x(WqWk^T)x^T + a_i + b_j + c ).
// Terms: 3-term (MT, t, scores), 2-term (v/out proj), 1-term (ctx).
// 128x128 tiles, 128 thr/4 warps, 64x64 warp tiles, 2 CTA/SM, per-variant
// cp.async depth, persistent-CTA scheduler.
// R11: dual-stream capture fork — v-proj + aux kernels overlap the
// low-parallelism MT GEMM (64 tiles) and the t chain.
// B=4, S=2048, D=1024.
// ============================================================================

#define TOK 8192
#define DIM 1024
#define SEQ 2048
#define BATCH 4

static const long long OUT_ELEMS = (long long)TOK * DIM;
static const long long PATTN_ELEMS = (long long)BATCH * SEQ * SEQ;

// ---------------- device scratch ----------------
__device__ __half g_xhi[TOK * DIM], g_xlo[TOK * DIM];
__device__ __half g_wqsh[DIM * DIM], g_wqsl[DIM * DIM];
__device__ __half g_wksh[DIM * DIM], g_wksl[DIM * DIM];
__device__ __half g_wvTh[DIM * DIM], g_wvTl[DIM * DIM];
__device__ __half g_wpTh[DIM * DIM], g_wpTl[DIM * DIM];
__device__ __half g_mth[DIM * DIM], g_mtl[DIM * DIM];
__device__ __half g_thi[TOK * DIM], g_tlo[TOK * DIM];
__device__ __half g_vThi[TOK * DIM];
__device__ __half g_phi[BATCH * SEQ * SEQ];
__device__ __half g_ctxhi[TOK * DIM];
__device__ float  g_u[DIM], g_w[DIM], g_c[1];
__device__ float  g_av[TOK], g_bv[TOK];
__device__ float  g_scores_fb[BATCH * SEQ * SEQ];

// ---------------- PTX helpers ----------------
__device__ __forceinline__ uint32_t smem_u32_f(const void* p) {
    uint32_t a;
    asm("{ .reg .u64 t; cvta.to.shared.u64 t, %1; cvt.u32.u64 %0, t; }"
        : "=r"(a) : "l"(p));
    return a;
}
__device__ __forceinline__ void cp16(uint32_t dst, const void* src) {
    asm volatile("cp.async.cg.shared.global [%0], [%1], 16;" :: "r"(dst), "l"(src));
}
__device__ __forceinline__ void cp_commit() { asm volatile("cp.async.commit_group;"); }
template <int N>
__device__ __forceinline__ void cp_wait() {
    asm volatile("cp.async.wait_group %0;" :: "n"(N));
}
__device__ __forceinline__ void ldm_x4(uint32_t r[4], uint32_t addr) {
    asm volatile("ldmatrix.sync.aligned.m8n8.x4.shared.b16 {%0,%1,%2,%3}, [%4];"
                 : "=r"(r[0]), "=r"(r[1]), "=r"(r[2]), "=r"(r[3]) : "r"(addr));
}
__device__ __forceinline__ void mma16816(float c[4], const uint32_t a[4],
                                         const uint32_t b0, const uint32_t b1) {
    asm volatile(
        "mma.sync.aligned.m16n8k16.row.col.f32.f16.f16.f32 "
        "{%0,%1,%2,%3},{%4,%5,%6,%7},{%8,%9},{%0,%1,%2,%3};"
        : "+f"(c[0]), "+f"(c[1]), "+f"(c[2]), "+f"(c[3])
        : "r"(a[0]), "r"(a[1]), "r"(a[2]), "r"(a[3]), "r"(b0), "r"(b1));
}

#define PITCH 80u
#define TILE_B (128u * PITCH)            // 10240 B

// ============================================================================
// GEMM core for one 128x128 output tile.
// ============================================================================
template <int NS, bool ASPLIT, bool BSPLIT, bool WF32, bool HASBIAS, bool WLO,
          bool WTRANS, bool SCB>
__device__ __forceinline__ void gemm_core(
    const __half* __restrict__ Ah, const __half* __restrict__ Al,
    const __half* __restrict__ Bh, const __half* __restrict__ Bl,
    const float* __restrict__ bias,
    float* __restrict__ Cf, __half* __restrict__ Chi, __half* __restrict__ Clo,
    int N, int K, float alpha, int row0, int col0, long long cOff,
    const float* __restrict__ av, const float* __restrict__ bv,
    const float* __restrict__ cb)
{
    constexpr uint32_t OF_AH = 0u;
    constexpr uint32_t OF_BH = TILE_B;
    constexpr uint32_t OF_AL = 2u * TILE_B;
    constexpr uint32_t OF_BL = (ASPLIT ? 3u : 2u) * TILE_B;
    constexpr uint32_t STG_SZ = (2u + (ASPLIT ? 1u : 0u) + (BSPLIT ? 1u : 0u)) * TILE_B;

    extern __shared__ char smem_raw[];
    const uint32_t base = smem_u32_f(smem_raw);
    const int tid = threadIdx.x;
    const int warp = tid >> 5, lane = tid & 31;

    long long aOff[4], bOff[4];
    uint32_t dOff[4];
#pragma unroll
    for (int j = 0; j < 4; j++) {
        int c = tid + j * 128;
        int r = c >> 2, q = c & 3;
        aOff[j] = (long long)(row0 + r) * K + q * 8;
        bOff[j] = (long long)(col0 + r) * K + q * 8;
        dOff[j] = (uint32_t)r * PITCH + (uint32_t)q * 16u;
    }

    const int m0 = (warp & 1) * 64, n0 = (warp >> 1) * 64;
    const uint32_t aLane = (uint32_t)(lane & 15) * PITCH + (uint32_t)(lane >> 4) * 16u;
    const uint32_t bLane = (uint32_t)((lane & 7) + ((lane >> 4) << 3)) * PITCH +
                           (uint32_t)((lane >> 3) & 1) * 16u;

    float acc[4][8][4];
#pragma unroll
    for (int i = 0; i < 4; i++)
#pragma unroll
        for (int j = 0; j < 8; j++)
#pragma unroll
            for (int e = 0; e < 4; e++) acc[i][j][e] = 0.f;

    const int nk = K >> 5;

#pragma unroll
    for (int s = 0; s < NS - 1; s++) {
        uint32_t sb = base + (uint32_t)s * STG_SZ;
        long long k0 = (long long)s * 32;
#pragma unroll
        for (int j = 0; j < 4; j++) {
            cp16(sb + OF_AH + dOff[j], Ah + aOff[j] + k0);
            if (ASPLIT) cp16(sb + OF_AL + dOff[j], Al + aOff[j] + k0);
            cp16(sb + OF_BH + dOff[j], Bh + bOff[j] + k0);
            if (BSPLIT) cp16(sb + OF_BL + dOff[j], Bl + bOff[j] + k0);
        }
        cp_commit();
    }

    for (int i = 0; i < nk; i++) {
        const int pend = (nk - 1 - i < NS - 2) ? (nk - 1 - i) : (NS - 2);
        if (pend >= 2)      cp_wait<2>();
        else if (pend == 1) cp_wait<1>();
        else                cp_wait<0>();
        __syncthreads();

        if (i + NS - 1 < nk) {
            const int s = (i + NS - 1) % NS;
            uint32_t sb = base + (uint32_t)s * STG_SZ;
            long long k0 = (long long)(i + NS - 1) * 32;
#pragma unroll
            for (int j = 0; j < 4; j++) {
                cp16(sb + OF_AH + dOff[j], Ah + aOff[j] + k0);
                if (ASPLIT) cp16(sb + OF_AL + dOff[j], Al + aOff[j] + k0);
                cp16(sb + OF_BH + dOff[j], Bh + bOff[j] + k0);
                if (BSPLIT) cp16(sb + OF_BL + dOff[j], Bl + bOff[j] + k0);
            }
            cp_commit();
        }

        const uint32_t sb = base + (uint32_t)(i % NS) * STG_SZ;
#pragma unroll
        for (int ks = 0; ks < 2; ks++) {
            const uint32_t kb = (uint32_t)ks * 32u;
            uint32_t ah[4][4], al[4][4], bh[4][4], bl[4][4];
#pragma unroll
            for (int mf = 0; mf < 4; mf++) {
                uint32_t ro = (uint32_t)(m0 + mf * 16) * PITCH + kb + aLane;
                ldm_x4(ah[mf], sb + OF_AH + ro);
                if (ASPLIT) ldm_x4(al[mf], sb + OF_AL + ro);
            }
#pragma unroll
            for (int q = 0; q < 4; q++) {
                uint32_t ro = (uint32_t)(n0 + q * 16) * PITCH + kb + bLane;
                ldm_x4(bh[q], sb + OF_BH + ro);
                if (BSPLIT) ldm_x4(bl[q], sb + OF_BL + ro);
            }
#pragma unroll
            for (int mf = 0; mf < 4; mf++)
#pragma unroll
                for (int nf = 0; nf < 8; nf++) {
                    const int q = nf >> 1, h = (nf & 1) * 2;
                    mma16816(acc[mf][nf], ah[mf], bh[q][h], bh[q][h + 1]);
                    if (ASPLIT) mma16816(acc[mf][nf], al[mf], bh[q][h], bh[q][h + 1]);
                    if (BSPLIT) mma16816(acc[mf][nf], ah[mf], bl[q][h], bl[q][h + 1]);
                }
        }
    }

    // ---- epilogue ----
    const int tg = lane >> 2, tl = lane & 3;
    const float c0 = SCB ? __ldg(cb) : 0.f;
#pragma unroll
    for (int mf = 0; mf < 4; mf++) {
#pragma unroll
        for (int nf = 0; nf < 8; nf++) {
            const int col = col0 + n0 + nf * 8 + tl * 2;
            float b0 = 0.f, b1 = 0.f;
            if (HASBIAS) { b0 = __ldg(bias + col); b1 = __ldg(bias + col + 1); }
            float bc0 = 0.f, bc1 = 0.f;
            if (SCB) { bc0 = __ldg(bv + col) + c0; bc1 = __ldg(bv + col + 1) + c0; }
#pragma unroll
            for (int hrow = 0; hrow < 2; hrow++) {
                const int row = row0 + m0 + mf * 16 + tg + hrow * 8;
                float v0, v1;
                if (SCB) {
                    const float ar = __ldg(av + row);
                    v0 = (acc[mf][nf][hrow * 2 + 0] + ar + bc0) * alpha;
                    v1 = (acc[mf][nf][hrow * 2 + 1] + ar + bc1) * alpha;
                } else {
                    v0 = acc[mf][nf][hrow * 2 + 0] * alpha + b0;
                    v1 = acc[mf][nf][hrow * 2 + 1] * alpha + b1;
                }
                if (WTRANS) {
                    Chi[cOff + (long long)col * SEQ + row] = __float2half_rn(v0);
                    Chi[cOff + (long long)(col + 1) * SEQ + row] = __float2half_rn(v1);
                } else {
                    const long long off = cOff + (long long)row * N + col;
                    if (WF32) {
                        float2 o; o.x = v0; o.y = v1;
                        *(float2*)(Cf + off) = o;
                    } else {
                        __half h0 = __float2half_rn(v0);
                        __half h1 = __float2half_rn(v1);
                        __half2 th; th.x = h0; th.y = h1;
                        *(__half2*)(Chi + off) = th;
                        if (WLO) {
                            __half2 tlh;
                            tlh.x = __float2half_rn(v0 - __half2float(h0));
                            tlh.y = __float2half_rn(v1 - __half2float(h1));
                            *(__half2*)(Clo + off) = tlh;
                        }
                    }
                }
            }
        }
    }
}

// ---------------- persistent GEMM over (ntz, nty, ntx) tiles ----------------
template <int NS, bool ASPLIT, bool BSPLIT, bool WF32, bool HASBIAS, bool WLO,
          bool SCB>
__global__ void __launch_bounds__(128) mma_gemm_p(
    const __half* __restrict__ Ah_g, const __half* __restrict__ Al_g,
    const __half* __restrict__ Bh_g, const __half* __restrict__ Bl_g,
    const float* __restrict__ bias,
    float* __restrict__ Cf, __half* __restrict__ Chi, __half* __restrict__ Clo,
    int N, int K, float alpha,
    long long sA, long long sB, long long sC,
    int ntx, int nty, int ntz,
    const float* __restrict__ av, const float* __restrict__ bv,
    const float* __restrict__ cb)
{
    const int total = ntx * nty * ntz;
    const int nxy = ntx * nty;
    for (int t = blockIdx.x; t < total; t += gridDim.x) {
        const int tz = t / nxy;
        const int r = t - tz * nxy;
        const int ty = r / ntx;
        const int tx = r - ty * ntx;
        __syncthreads();
        gemm_core<NS, ASPLIT, BSPLIT, WF32, HASBIAS, WLO, false, SCB>(
            Ah_g + (long long)tz * sA, ASPLIT ? (Al_g + (long long)tz * sA) : nullptr,
            Bh_g + (long long)tz * sB, BSPLIT ? (Bl_g + (long long)tz * sB) : nullptr,
            bias, Cf, Chi, Clo, N, K, alpha,
            ty * 128, tx * 128, (long long)tz * sC,
            SCB ? (av + (long long)tz * SEQ) : nullptr,
            SCB ? (bv + (long long)tz * SEQ) : nullptr, cb);
    }
}

// persistent v projection: v = x @ Wv (2-term, 3-stage, transposed out -> vT)
__global__ void __launch_bounds__(128) v_gemm_p(
    const __half* __restrict__ xhi,
    const __half* __restrict__ wvTh, const __half* __restrict__ wvTl,
    const float* __restrict__ bvb,
    __half* __restrict__ vThi,
    int ntx, int nty)
{
    const int total = ntx * nty;
    for (int t = blockIdx.x; t < total; t += gridDim.x) {
        const int ty = t / ntx;
        const int tx = t - ty * ntx;
        __syncthreads();
        const long long batch = (long long)((ty * 128) >> 11);
        gemm_core<3, false, true, false, true, false, true, false>(
            xhi, nullptr, wvTh, wvTl, bvb,
            nullptr, vThi, nullptr, DIM, DIM, 1.f,
            ty * 128, tx * 128, batch * SEQ * (DIM - 1),
            nullptr, nullptr, nullptr);
    }
}

// smem budgets
#define SMEM_3T  (2 * 4 * 10240)        // 81920
#define SMEM_2T  (3 * 3 * 10240)        // 92160
#define SMEM_1T  (4 * 2 * 10240)        // 81920

// ============================================================================
// helper kernels
// ============================================================================
__global__ void __launch_bounds__(256) convert_split_kernel(
    const float* __restrict__ in, __half* __restrict__ hi,
    __half* __restrict__ lo, long long n4)
{
    long long i = (long long)blockIdx.x * 256 + threadIdx.x;
    if (i >= n4) return;
    float4 v = ((const float4*)in)[i];
    __half h0 = __float2half_rn(v.x), h1 = __float2half_rn(v.y);
    __half h2 = __float2half_rn(v.z), h3 = __float2half_rn(v.w);
    __half2 a, b; a.x = h0; a.y = h1; b.x = h2; b.y = h3;
    ((__half2*)hi)[i * 2 + 0] = a;
    ((__half2*)hi)[i * 2 + 1] = b;
    __half2 c, d;
    c.x = __float2half_rn(v.x - __half2float(h0));
    c.y = __float2half_rn(v.y - __half2float(h1));
    d.x = __float2half_rn(v.z - __half2float(h2));
    d.y = __float2half_rn(v.w - __half2float(h3));
    ((__half2*)lo)[i * 2 + 0] = c;
    ((__half2*)lo)[i * 2 + 1] = d;
}

__global__ void __launch_bounds__(256) transpose_split_kernel(
    const float* __restrict__ in, __half* __restrict__ hi,
    __half* __restrict__ lo, int R, int C)
{
    __shared__ float t[32][33];
    const int c0 = blockIdx.x * 32, r0 = blockIdx.y * 32;
    const int tx = threadIdx.x & 31, ty = threadIdx.x >> 5;
#pragma unroll
    for (int j = 0; j < 4; j++)
        t[ty + j * 8][tx] = in[(long long)(r0 + ty + j * 8) * C + c0 + tx];
    __syncthreads();
#pragma unroll
    for (int j = 0; j < 4; j++) {
        int oc = c0 + ty + j * 8;
        float v = t[tx][ty + j * 8];
        long long o = (long long)oc * R + r0 + tx;
        __half h = __float2half_rn(v);
        hi[o] = h;
        lo[o] = __float2half_rn(v - __half2float(h));
    }
}

__global__ void __launch_bounds__(256) uvw_kernel(
    const float* __restrict__ wq, const float* __restrict__ wk,
    const float* __restrict__ bq, const float* __restrict__ bk,
    float* __restrict__ u, float* __restrict__ w, float* __restrict__ cb)
{
    const int d = blockIdx.x;
    const int tid = threadIdx.x;
    float su = 0.f, sw = 0.f;
    for (int f = tid; f < DIM; f += 256) {
        su += wq[(long long)d * DIM + f] * bk[f];
        sw += wk[(long long)d * DIM + f] * bq[f];
    }
    __shared__ float r1[256], r2[256];
    r1[tid] = su; r2[tid] = sw;
    __syncthreads();
    for (int s = 128; s; s >>= 1) {
        if (tid < s) { r1[tid] += r1[tid + s]; r2[tid] += r2[tid + s]; }
        __syncthreads();
    }
    if (tid == 0) { u[d] = r1[0]; w[d] = r2[0]; }
    if (d == 0 && tid == 0) {
        float c = 0.f;
        for (int f = 0; f < DIM; f++) c += bq[f] * bk[f];
        cb[0] = c;
    }
}

__global__ void __launch_bounds__(256) av_kernel(
    const float* __restrict__ x, const float* __restrict__ u,
    const float* __restrict__ w, float* __restrict__ av, float* __restrict__ bv)
{
    const long long i = blockIdx.x;
    const float* xr = x + i * DIM;
    const int tid = threadIdx.x;
    float sa = 0.f, sb = 0.f;
    for (int d = tid; d < DIM; d += 256) {
        float xv = xr[d];
        sa += xv * u[d];
        sb += xv * w[d];
    }
    __shared__ float r1[256], r2[256];
    r1[tid] = sa; r2[tid] = sb;
    __syncthreads();
    for (int s = 128; s; s >>= 1) {
        if (tid < s) { r1[tid] += r1[tid + s]; r2[tid] += r2[tid + s]; }
        __syncthreads();
    }
    if (tid == 0) { av[i] = r1[0]; bv[i] = r2[0]; }
}

__global__ void __launch_bounds__(256) softmax2048_kernel(
    float* __restrict__ p, __half* __restrict__ phi)
{
    const long long roff = (long long)blockIdx.x * 2048;
    float* row = p + roff;
    const int tid = threadIdx.x;

    float4 v0 = ((const float4*)row)[tid];
    float4 v1 = ((const float4*)row)[tid + 256];

    float m = fmaxf(fmaxf(fmaxf(v0.x, v0.y), fmaxf(v0.z, v0.w)),
                    fmaxf(fmaxf(v1.x, v1.y), fmaxf(v1.z, v1.w)));
    __shared__ float red[8];
#pragma unroll
    for (int o = 16; o; o >>= 1) m = fmaxf(m, __shfl_xor_sync(0xffffffffu, m, o));
    if ((tid & 31) == 0) red[tid >> 5] = m;
    __syncthreads();
    m = red[0];
#pragma unroll
    for (int i = 1; i < 8; i++) m = fmaxf(m, red[i]);
    __syncthreads();

    v0.x = expf(v0.x - m); v0.y = expf(v0.y - m);
    v0.z = expf(v0.z - m); v0.w = expf(v0.w - m);
    v1.x = expf(v1.x - m); v1.y = expf(v1.y - m);
    v1.z = expf(v1.z - m); v1.w = expf(v1.w - m);

    float s = (v0.x + v0.y) + (v0.z + v0.w) + (v1.x + v1.y) + (v1.z + v1.w);
#pragma unroll
    for (int o = 16; o; o >>= 1) s += __shfl_xor_sync(0xffffffffu, s, o);
    if ((tid & 31) == 0) red[tid >> 5] = s;
    __syncthreads();
    s = ((red[0] + red[1]) + (red[2] + red[3])) +
        ((red[4] + red[5]) + (red[6] + red[7]));
    float inv = 1.0f / s;

    v0.x *= inv; v0.y *= inv; v0.z *= inv; v0.w *= inv;
    v1.x *= inv; v1.y *= inv; v1.z *= inv; v1.w *= inv;

    ((float4*)row)[tid] = v0;
    ((float4*)row)[tid + 256] = v1;

    const float vv[8] = {v0.x, v0.y, v0.z, v0.w, v1.x, v1.y, v1.z, v1.w};
    const long long off[2] = {roff + (long long)tid * 4,
                              roff + (long long)(tid + 256) * 4};
#pragma unroll
    for (int hseg = 0; hseg < 2; hseg++) {
#pragma unroll
        for (int g = 0; g < 2; g++) {
            __half2 th;
            th.x = __float2half_rn(vv[hseg * 4 + g * 2]);
            th.y = __float2half_rn(vv[hseg * 4 + g * 2 + 1]);
            *(__half2*)(phi + off[hseg] + g * 2) = th;
        }
    }
}

// ============================================================================
// host launcher
// ============================================================================
extern "C" void kernel_launch(void* const* d_in, const int* in_sizes, int n_in,
                              void* d_out, int out_size)
{
    const float* x  = (const float*)d_in[0];
    const float* wq = (const float*)d_in[1];
    const float* bq = (const float*)d_in[2];
    const float* wk = (const float*)d_in[3];
    const float* bk = (const float*)d_in[4];
    const float* wv = (const float*)d_in[5];
    const float* bv = (const float*)d_in[6];
    const float* wp = (const float*)d_in[7];
    const float* bp = (const float*)d_in[8];
    float* out = (float*)d_out;

#define SYM(p, s) void* p##_; cudaGetSymbolAddress(&p##_, s);
    SYM(xhi, g_xhi) SYM(xlo, g_xlo)
    SYM(wqsh, g_wqsh) SYM(wqsl, g_wqsl)
    SYM(wksh, g_wksh) SYM(wksl, g_wksl)
    SYM(wvth, g_wvTh) SYM(wvtl, g_wvTl)
    SYM(wpth, g_wpTh) SYM(wptl, g_wpTl)
    SYM(mth, g_mth) SYM(mtl, g_mtl)
    SYM(thi, g_thi) SYM(tlo, g_tlo)
    SYM(vth, g_vThi)
    SYM(phi, g_phi)
    SYM(cxh, g_ctxhi)
    SYM(uu, g_u) SYM(ww, g_w) SYM(cc, g_c)
    SYM(avv, g_av) SYM(bvv, g_bv)
    SYM(sfb, g_scores_fb)
#undef SYM
#define HF(p) ((__half*)p##_)

    float* pattn = (out_size >= (long long)(OUT_ELEMS + PATTN_ELEMS))
                       ? (out + OUT_ELEMS) : (float*)sfb_;

    static int nPersist = 0;
    static cudaStream_t s1 = nullptr;
    static cudaEvent_t evFork = nullptr, evX = nullptr, evJoin = nullptr;
    if (nPersist == 0) {
        int nsm = 148;
        cudaDeviceGetAttribute(&nsm, cudaDevAttrMultiProcessorCount, 0);
        nPersist = 2 * nsm;
        cudaStreamCreateWithFlags(&s1, cudaStreamNonBlocking);
        cudaEventCreateWithFlags(&evFork, cudaEventDisableTiming);
        cudaEventCreateWithFlags(&evX, cudaEventDisableTiming);
        cudaEventCreateWithFlags(&evJoin, cudaEventDisableTiming);

        cudaFuncSetAttribute(v_gemm_p, cudaFuncAttributeMaxDynamicSharedMemorySize, SMEM_2T);
        cudaFuncSetAttribute(mma_gemm_p<2, true,  true,  false, false, true,  false>, cudaFuncAttributeMaxDynamicSharedMemorySize, SMEM_3T);
        cudaFuncSetAttribute(mma_gemm_p<2, true,  true,  true,  false, false, true >, cudaFuncAttributeMaxDynamicSharedMemorySize, SMEM_3T);
        cudaFuncSetAttribute(mma_gemm_p<4, false, false, false, false, false, false>, cudaFuncAttributeMaxDynamicSharedMemorySize, SMEM_1T);
        cudaFuncSetAttribute(mma_gemm_p<3, false, true,  true,  true,  false, false>, cudaFuncAttributeMaxDynamicSharedMemorySize, SMEM_2T);
    }
    cudaStream_t s0 = 0;

    // ---- fork ----
    cudaEventRecord(evFork, s0);
    cudaStreamWaitEvent(s1, evFork, 0);

    // ---- s0: critical chain (x split -> wq/wk splits -> MT -> t) ----
    convert_split_kernel<<<(TOK * DIM / 4 + 255) / 256, 256, 0, s0>>>(
        x, HF(xhi), HF(xlo), TOK * DIM / 4);
    cudaEventRecord(evX, s0);
    convert_split_kernel<<<(DIM * DIM / 4 + 255) / 256, 256, 0, s0>>>(
        wq, HF(wqsh), HF(wqsl), DIM * DIM / 4);
    convert_split_kernel<<<(DIM * DIM / 4 + 255) / 256, 256, 0, s0>>>(
        wk, HF(wksh), HF(wksl), DIM * DIM / 4);

    // MT = Wk @ Wq^T (3-term, hi/lo out; 64 tiles)
    mma_gemm_p<2, true, true, false, false, true, false><<<64, 128, SMEM_3T, s0>>>(
        HF(wksh), HF(wksl), HF(wqsh), HF(wqsl), nullptr,
        nullptr, HF(mth), HF(mtl), DIM, DIM, 1.f, 0, 0, 0,
        DIM / 128, DIM / 128, 1, nullptr, nullptr, nullptr);

    // t = x @ MT^T (3-term, hi/lo out; 512 tiles)
    mma_gemm_p<2, true, true, false, false, true, false><<<nPersist, 128, SMEM_3T, s0>>>(
        HF(xhi), HF(xlo), HF(mth), HF(mtl), nullptr,
        nullptr, HF(thi), HF(tlo), DIM, DIM, 1.f, 0, 0, 0,
        DIM / 128, TOK / 128, 1, nullptr, nullptr, nullptr);

    // ---- s1: independent work (overlaps MT + t) ----
    dim3 gW(DIM / 32, DIM / 32, 1);
    transpose_split_kernel<<<gW, 256, 0, s1>>>(wv, HF(wvth), HF(wvtl), DIM, DIM);
    transpose_split_kernel<<<gW, 256, 0, s1>>>(wp, HF(wpth), HF(wptl), DIM, DIM);
    uvw_kernel<<<DIM, 256, 0, s1>>>(wq, wk, bq, bk, (float*)uu_, (float*)ww_, (float*)cc_);
    av_kernel<<<TOK, 256, 0, s1>>>(x, (float*)uu_, (float*)ww_, (float*)avv_, (float*)bvv_);
    cudaStreamWaitEvent(s1, evX, 0);   // v needs xhi
    v_gemm_p<<<nPersist, 128, SMEM_2T, s1>>>(
        HF(xhi), HF(wvth), HF(wvtl), bv, HF(vth), DIM / 128, TOK / 128);
    cudaEventRecord(evJoin, s1);

    // ---- join, then tail on s0 ----
    cudaStreamWaitEvent(s0, evJoin, 0);

    // scores = 32*(t @ x^T + a_i + b_j + c) per batch
    mma_gemm_p<2, true, true, true, false, false, true><<<nPersist, 128, SMEM_3T, s0>>>(
        HF(thi), HF(tlo), HF(xhi), HF(xlo), nullptr, pattn, nullptr, nullptr,
        SEQ, DIM, 32.f,
        (long long)SEQ * DIM, (long long)SEQ * DIM, (long long)SEQ * SEQ,
        SEQ / 128, SEQ / 128, BATCH,
        (const float*)avv_, (const float*)bvv_, (const float*)cc_);

    softmax2048_kernel<<<TOK, 256, 0, s0>>>(pattn, HF(phi));

    // ctx = p_hi @ v_hi (1-term, 4-stage)
    mma_gemm_p<4, false, false, false, false, false, false><<<nPersist, 128, SMEM_1T, s0>>>(
        HF(phi), nullptr, HF(vth), nullptr, nullptr, nullptr, HF(cxh), nullptr,
        DIM, SEQ, 1.f,
        (long long)SEQ * SEQ, (long long)DIM * SEQ, (long long)SEQ * DIM,
        DIM / 128, SEQ / 128, BATCH, nullptr, nullptr, nullptr);

    // out = ctx_hi @ (wp_hi + wp_lo) + bp (2-term, 3-stage)
    mma_gemm_p<3, false, true, true, true, false, false><<<nPersist, 128, SMEM_2T, s0>>>(
        HF(cxh), nullptr, HF(wpth), HF(wptl), bp, out, nullptr, nullptr,
        DIM, DIM, 1.f, 0, 0, 0,
        DIM / 128, TOK / 128, 1, nullptr, nullptr, nullptr);
}

// round 12
// speedup vs baseline: 1.2625x; 1.0138x over previous
#include <cuda_runtime.h>
#include <cuda_fp16.h>
#include <cstdint>

// ============================================================================
// Fused attention block via mma.sync (HMMA), fp16 hi/lo split arithmetic.
// Algebraic rewrite: scores = 32*( x(WqWk^T)x^T + a_i + b_j + c ).
// R12: split-K MT (4x256 chunks -> fp32 partials -> reduce) for full
// occupancy on the critical path; x-split moved to the side stream.
// Terms: 3-term (MT, t, scores), 2-term (v/out proj), 1-term (ctx).
// 128x128 tiles, 128 thr/4 warps, 64x64 warp tiles, 2 CTA/SM.
// ============================================================================

#define TOK 8192
#define DIM 1024
#define SEQ 2048
#define BATCH 4

static const long long OUT_ELEMS = (long long)TOK * DIM;
static const long long PATTN_ELEMS = (long long)BATCH * SEQ * SEQ;

// ---------------- device scratch ----------------
__device__ __half g_xhi[TOK * DIM], g_xlo[TOK * DIM];
__device__ __half g_wqsh[DIM * DIM], g_wqsl[DIM * DIM];
__device__ __half g_wksh[DIM * DIM], g_wksl[DIM * DIM];
__device__ __half g_wvTh[DIM * DIM], g_wvTl[DIM * DIM];
__device__ __half g_wpTh[DIM * DIM], g_wpTl[DIM * DIM];
__device__ float  g_mtpart[4 * DIM * DIM];                // split-K partials
__device__ __half g_mth[DIM * DIM], g_mtl[DIM * DIM];
__device__ __half g_thi[TOK * DIM], g_tlo[TOK * DIM];
__device__ __half g_vThi[TOK * DIM];
__device__ __half g_phi[BATCH * SEQ * SEQ];
__device__ __half g_ctxhi[TOK * DIM];
__device__ float  g_u[DIM], g_w[DIM], g_c[1];
__device__ float  g_av[TOK], g_bv[TOK];
__device__ float  g_scores_fb[BATCH * SEQ * SEQ];

// ---------------- PTX helpers ----------------
__device__ __forceinline__ uint32_t smem_u32_f(const void* p) {
    uint32_t a;
    asm("{ .reg .u64 t; cvta.to.shared.u64 t, %1; cvt.u32.u64 %0, t; }"
        : "=r"(a) : "l"(p));
    return a;
}
__device__ __forceinline__ void cp16(uint32_t dst, const void* src) {
    asm volatile("cp.async.cg.shared.global [%0], [%1], 16;" :: "r"(dst), "l"(src));
}
__device__ __forceinline__ void cp_commit() { asm volatile("cp.async.commit_group;"); }
template <int N>
__device__ __forceinline__ void cp_wait() {
    asm volatile("cp.async.wait_group %0;" :: "n"(N));
}
__device__ __forceinline__ void ldm_x4(uint32_t r[4], uint32_t addr) {
    asm volatile("ldmatrix.sync.aligned.m8n8.x4.shared.b16 {%0,%1,%2,%3}, [%4];"
                 : "=r"(r[0]), "=r"(r[1]), "=r"(r[2]), "=r"(r[3]) : "r"(addr));
}
__device__ __forceinline__ void mma16816(float c[4], const uint32_t a[4],
                                         const uint32_t b0, const uint32_t b1) {
    asm volatile(
        "mma.sync.aligned.m16n8k16.row.col.f32.f16.f16.f32 "
        "{%0,%1,%2,%3},{%4,%5,%6,%7},{%8,%9},{%0,%1,%2,%3};"
        : "+f"(c[0]), "+f"(c[1]), "+f"(c[2]), "+f"(c[3])
        : "r"(a[0]), "r"(a[1]), "r"(a[2]), "r"(a[3]), "r"(b0), "r"(b1));
}

#define PITCH 80u
#define TILE_B (128u * PITCH)            // 10240 B

// ============================================================================
// GEMM core for one 128x128 output tile.
// Kld = row stride of A/B; Kit = K extent actually iterated (split-K).
// ============================================================================
template <int NS, bool ASPLIT, bool BSPLIT, bool WF32, bool HASBIAS, bool WLO,
          bool WTRANS, bool SCB>
__device__ __forceinline__ void gemm_core(
    const __half* __restrict__ Ah, const __half* __restrict__ Al,
    const __half* __restrict__ Bh, const __half* __restrict__ Bl,
    const float* __restrict__ bias,
    float* __restrict__ Cf, __half* __restrict__ Chi, __half* __restrict__ Clo,
    int N, int Kld, int Kit, float alpha, int row0, int col0, long long cOff,
    const float* __restrict__ av, const float* __restrict__ bv,
    const float* __restrict__ cb)
{
    constexpr uint32_t OF_AH = 0u;
    constexpr uint32_t OF_BH = TILE_B;
    constexpr uint32_t OF_AL = 2u * TILE_B;
    constexpr uint32_t OF_BL = (ASPLIT ? 3u : 2u) * TILE_B;
    constexpr uint32_t STG_SZ = (2u + (ASPLIT ? 1u : 0u) + (BSPLIT ? 1u : 0u)) * TILE_B;

    extern __shared__ char smem_raw[];
    const uint32_t base = smem_u32_f(smem_raw);
    const int tid = threadIdx.x;
    const int warp = tid >> 5, lane = tid & 31;

    long long aOff[4], bOff[4];
    uint32_t dOff[4];
#pragma unroll
    for (int j = 0; j < 4; j++) {
        int c = tid + j * 128;
        int r = c >> 2, q = c & 3;
        aOff[j] = (long long)(row0 + r) * Kld + q * 8;
        bOff[j] = (long long)(col0 + r) * Kld + q * 8;
        dOff[j] = (uint32_t)r * PITCH + (uint32_t)q * 16u;
    }

    const int m0 = (warp & 1) * 64, n0 = (warp >> 1) * 64;
    const uint32_t aLane = (uint32_t)(lane & 15) * PITCH + (uint32_t)(lane >> 4) * 16u;
    const uint32_t bLane = (uint32_t)((lane & 7) + ((lane >> 4) << 3)) * PITCH +
                           (uint32_t)((lane >> 3) & 1) * 16u;

    float acc[4][8][4];
#pragma unroll
    for (int i = 0; i < 4; i++)
#pragma unroll
        for (int j = 0; j < 8; j++)
#pragma unroll
            for (int e = 0; e < 4; e++) acc[i][j][e] = 0.f;

    const int nk = Kit >> 5;

#pragma unroll
    for (int s = 0; s < NS - 1; s++) {
        uint32_t sb = base + (uint32_t)s * STG_SZ;
        long long k0 = (long long)s * 32;
#pragma unroll
        for (int j = 0; j < 4; j++) {
            cp16(sb + OF_AH + dOff[j], Ah + aOff[j] + k0);
            if (ASPLIT) cp16(sb + OF_AL + dOff[j], Al + aOff[j] + k0);
            cp16(sb + OF_BH + dOff[j], Bh + bOff[j] + k0);
            if (BSPLIT) cp16(sb + OF_BL + dOff[j], Bl + bOff[j] + k0);
        }
        cp_commit();
    }

    for (int i = 0; i < nk; i++) {
        const int pend = (nk - 1 - i < NS - 2) ? (nk - 1 - i) : (NS - 2);
        if (pend >= 2)      cp_wait<2>();
        else if (pend == 1) cp_wait<1>();
        else                cp_wait<0>();
        __syncthreads();

        if (i + NS - 1 < nk) {
            const int s = (i + NS - 1) % NS;
            uint32_t sb = base + (uint32_t)s * STG_SZ;
            long long k0 = (long long)(i + NS - 1) * 32;
#pragma unroll
            for (int j = 0; j < 4; j++) {
                cp16(sb + OF_AH + dOff[j], Ah + aOff[j] + k0);
                if (ASPLIT) cp16(sb + OF_AL + dOff[j], Al + aOff[j] + k0);
                cp16(sb + OF_BH + dOff[j], Bh + bOff[j] + k0);
                if (BSPLIT) cp16(sb + OF_BL + dOff[j], Bl + bOff[j] + k0);
            }
            cp_commit();
        }

        const uint32_t sb = base + (uint32_t)(i % NS) * STG_SZ;
#pragma unroll
        for (int ks = 0; ks < 2; ks++) {
            const uint32_t kb = (uint32_t)ks * 32u;
            uint32_t ah[4][4], al[4][4], bh[4][4], bl[4][4];
#pragma unroll
            for (int mf = 0; mf < 4; mf++) {
                uint32_t ro = (uint32_t)(m0 + mf * 16) * PITCH + kb + aLane;
                ldm_x4(ah[mf], sb + OF_AH + ro);
                if (ASPLIT) ldm_x4(al[mf], sb + OF_AL + ro);
            }
#pragma unroll
            for (int q = 0; q < 4; q++) {
                uint32_t ro = (uint32_t)(n0 + q * 16) * PITCH + kb + bLane;
                ldm_x4(bh[q], sb + OF_BH + ro);
                if (BSPLIT) ldm_x4(bl[q], sb + OF_BL + ro);
            }
#pragma unroll
            for (int mf = 0; mf < 4; mf++)
#pragma unroll
                for (int nf = 0; nf < 8; nf++) {
                    const int q = nf >> 1, h = (nf & 1) * 2;
                    mma16816(acc[mf][nf], ah[mf], bh[q][h], bh[q][h + 1]);
                    if (ASPLIT) mma16816(acc[mf][nf], al[mf], bh[q][h], bh[q][h + 1]);
                    if (BSPLIT) mma16816(acc[mf][nf], ah[mf], bl[q][h], bl[q][h + 1]);
                }
        }
    }

    // ---- epilogue ----
    const int tg = lane >> 2, tl = lane & 3;
    const float c0 = SCB ? __ldg(cb) : 0.f;
#pragma unroll
    for (int mf = 0; mf < 4; mf++) {
#pragma unroll
        for (int nf = 0; nf < 8; nf++) {
            const int col = col0 + n0 + nf * 8 + tl * 2;
            float b0 = 0.f, b1 = 0.f;
            if (HASBIAS) { b0 = __ldg(bias + col); b1 = __ldg(bias + col + 1); }
            float bc0 = 0.f, bc1 = 0.f;
            if (SCB) { bc0 = __ldg(bv + col) + c0; bc1 = __ldg(bv + col + 1) + c0; }
#pragma unroll
            for (int hrow = 0; hrow < 2; hrow++) {
                const int row = row0 + m0 + mf * 16 + tg + hrow * 8;
                float v0, v1;
                if (SCB) {
                    const float ar = __ldg(av + row);
                    v0 = (acc[mf][nf][hrow * 2 + 0] + ar + bc0) * alpha;
                    v1 = (acc[mf][nf][hrow * 2 + 1] + ar + bc1) * alpha;
                } else {
                    v0 = acc[mf][nf][hrow * 2 + 0] * alpha + b0;
                    v1 = acc[mf][nf][hrow * 2 + 1] * alpha + b1;
                }
                if (WTRANS) {
                    Chi[cOff + (long long)col * SEQ + row] = __float2half_rn(v0);
                    Chi[cOff + (long long)(col + 1) * SEQ + row] = __float2half_rn(v1);
                } else {
                    const long long off = cOff + (long long)row * N + col;
                    if (WF32) {
                        float2 o; o.x = v0; o.y = v1;
                        *(float2*)(Cf + off) = o;
                    } else {
                        __half h0 = __float2half_rn(v0);
                        __half h1 = __float2half_rn(v1);
                        __half2 th; th.x = h0; th.y = h1;
                        *(__half2*)(Chi + off) = th;
                        if (WLO) {
                            __half2 tlh;
                            tlh.x = __float2half_rn(v0 - __half2float(h0));
                            tlh.y = __float2half_rn(v1 - __half2float(h1));
                            *(__half2*)(Clo + off) = tlh;
                        }
                    }
                }
            }
        }
    }
}

// ---------------- persistent GEMM over (ntz, nty, ntx) tiles ----------------
template <int NS, bool ASPLIT, bool BSPLIT, bool WF32, bool HASBIAS, bool WLO,
          bool SCB>
__global__ void __launch_bounds__(128) mma_gemm_p(
    const __half* __restrict__ Ah_g, const __half* __restrict__ Al_g,
    const __half* __restrict__ Bh_g, const __half* __restrict__ Bl_g,
    const float* __restrict__ bias,
    float* __restrict__ Cf, __half* __restrict__ Chi, __half* __restrict__ Clo,
    int N, int Kld, int Kit, float alpha,
    long long sA, long long sB, long long sC,
    int ntx, int nty, int ntz,
    const float* __restrict__ av, const float* __restrict__ bv,
    const float* __restrict__ cb)
{
    const int total = ntx * nty * ntz;
    const int nxy = ntx * nty;
    for (int t = blockIdx.x; t < total; t += gridDim.x) {
        const int tz = t / nxy;
        const int r = t - tz * nxy;
        const int ty = r / ntx;
        const int tx = r - ty * ntx;
        __syncthreads();
        gemm_core<NS, ASPLIT, BSPLIT, WF32, HASBIAS, WLO, false, SCB>(
            Ah_g + (long long)tz * sA, ASPLIT ? (Al_g + (long long)tz * sA) : nullptr,
            Bh_g + (long long)tz * sB, BSPLIT ? (Bl_g + (long long)tz * sB) : nullptr,
            bias, Cf, Chi, Clo, N, Kld, Kit, alpha,
            ty * 128, tx * 128, (long long)tz * sC,
            SCB ? (av + (long long)tz * SEQ) : nullptr,
            SCB ? (bv + (long long)tz * SEQ) : nullptr, cb);
    }
}

// persistent v projection: v = x @ Wv (2-term, 3-stage, transposed out -> vT)
__global__ void __launch_bounds__(128) v_gemm_p(
    const __half* __restrict__ xhi,
    const __half* __restrict__ wvTh, const __half* __restrict__ wvTl,
    const float* __restrict__ bvb,
    __half* __restrict__ vThi,
    int ntx, int nty)
{
    const int total = ntx * nty;
    for (int t = blockIdx.x; t < total; t += gridDim.x) {
        const int ty = t / ntx;
        const int tx = t - ty * ntx;
        __syncthreads();
        const long long batch = (long long)((ty * 128) >> 11);
        gemm_core<3, false, true, false, true, false, true, false>(
            xhi, nullptr, wvTh, wvTl, bvb,
            nullptr, vThi, nullptr, DIM, DIM, DIM, 1.f,
            ty * 128, tx * 128, batch * SEQ * (DIM - 1),
            nullptr, nullptr, nullptr);
    }
}

// smem budgets
#define SMEM_3T  (2 * 4 * 10240)        // 81920
#define SMEM_2T  (3 * 3 * 10240)        // 92160
#define SMEM_1T  (4 * 2 * 10240)        // 81920

// ============================================================================
// helper kernels
// ============================================================================
__global__ void __launch_bounds__(256) convert_split_kernel(
    const float* __restrict__ in, __half* __restrict__ hi,
    __half* __restrict__ lo, long long n4)
{
    long long i = (long long)blockIdx.x * 256 + threadIdx.x;
    if (i >= n4) return;
    float4 v = ((const float4*)in)[i];
    __half h0 = __float2half_rn(v.x), h1 = __float2half_rn(v.y);
    __half h2 = __float2half_rn(v.z), h3 = __float2half_rn(v.w);
    __half2 a, b; a.x = h0; a.y = h1; b.x = h2; b.y = h3;
    ((__half2*)hi)[i * 2 + 0] = a;
    ((__half2*)hi)[i * 2 + 1] = b;
    __half2 c, d;
    c.x = __float2half_rn(v.x - __half2float(h0));
    c.y = __float2half_rn(v.y - __half2float(h1));
    d.x = __float2half_rn(v.z - __half2float(h2));
    d.y = __float2half_rn(v.w - __half2float(h3));
    ((__half2*)lo)[i * 2 + 0] = c;
    ((__half2*)lo)[i * 2 + 1] = d;
}

// reduce 4 fp32 split-K partials -> hi/lo fp16 splits
__global__ void __launch_bounds__(256) mt_reduce_kernel(
    const float* __restrict__ part, __half* __restrict__ hi,
    __half* __restrict__ lo)
{
    const long long n4 = (long long)DIM * DIM / 4;
    long long i = (long long)blockIdx.x * 256 + threadIdx.x;
    if (i >= n4) return;
    const long long stride4 = n4;
    float4 a = ((const float4*)part)[i];
    float4 b = ((const float4*)part)[i + stride4];
    float4 c = ((const float4*)part)[i + 2 * stride4];
    float4 d = ((const float4*)part)[i + 3 * stride4];
    float4 s;
    s.x = (a.x + b.x) + (c.x + d.x);
    s.y = (a.y + b.y) + (c.y + d.y);
    s.z = (a.z + b.z) + (c.z + d.z);
    s.w = (a.w + b.w) + (c.w + d.w);
    __half h0 = __float2half_rn(s.x), h1 = __float2half_rn(s.y);
    __half h2 = __float2half_rn(s.z), h3 = __float2half_rn(s.w);
    __half2 p, q; p.x = h0; p.y = h1; q.x = h2; q.y = h3;
    ((__half2*)hi)[i * 2 + 0] = p;
    ((__half2*)hi)[i * 2 + 1] = q;
    __half2 r, t;
    r.x = __float2half_rn(s.x - __half2float(h0));
    r.y = __float2half_rn(s.y - __half2float(h1));
    t.x = __float2half_rn(s.z - __half2float(h2));
    t.y = __float2half_rn(s.w - __half2float(h3));
    ((__half2*)lo)[i * 2 + 0] = r;
    ((__half2*)lo)[i * 2 + 1] = t;
}

__global__ void __launch_bounds__(256) transpose_split_kernel(
    const float* __restrict__ in, __half* __restrict__ hi,
    __half* __restrict__ lo, int R, int C)
{
    __shared__ float t[32][33];
    const int c0 = blockIdx.x * 32, r0 = blockIdx.y * 32;
    const int tx = threadIdx.x & 31, ty = threadIdx.x >> 5;
#pragma unroll
    for (int j = 0; j < 4; j++)
        t[ty + j * 8][tx] = in[(long long)(r0 + ty + j * 8) * C + c0 + tx];
    __syncthreads();
#pragma unroll
    for (int j = 0; j < 4; j++) {
        int oc = c0 + ty + j * 8;
        float v = t[tx][ty + j * 8];
        long long o = (long long)oc * R + r0 + tx;
        __half h = __float2half_rn(v);
        hi[o] = h;
        lo[o] = __float2half_rn(v - __half2float(h));
    }
}

__global__ void __launch_bounds__(256) uvw_kernel(
    const float* __restrict__ wq, const float* __restrict__ wk,
    const float* __restrict__ bq, const float* __restrict__ bk,
    float* __restrict__ u, float* __restrict__ w, float* __restrict__ cb)
{
    const int d = blockIdx.x;
    const int tid = threadIdx.x;
    float su = 0.f, sw = 0.f;
    for (int f = tid; f < DIM; f += 256) {
        su += wq[(long long)d * DIM + f] * bk[f];
        sw += wk[(long long)d * DIM + f] * bq[f];
    }
    __shared__ float r1[256], r2[256];
    r1[tid] = su; r2[tid] = sw;
    __syncthreads();
    for (int s = 128; s; s >>= 1) {
        if (tid < s) { r1[tid] += r1[tid + s]; r2[tid] += r2[tid + s]; }
        __syncthreads();
    }
    if (tid == 0) { u[d] = r1[0]; w[d] = r2[0]; }
    if (d == 0 && tid == 0) {
        float c = 0.f;
        for (int f = 0; f < DIM; f++) c += bq[f] * bk[f];
        cb[0] = c;
    }
}

__global__ void __launch_bounds__(256) av_kernel(
    const float* __restrict__ x, const float* __restrict__ u,
    const float* __restrict__ w, float* __restrict__ av, float* __restrict__ bv)
{
    const long long i = blockIdx.x;
    const float* xr = x + i * DIM;
    const int tid = threadIdx.x;
    float sa = 0.f, sb = 0.f;
    for (int d = tid; d < DIM; d += 256) {
        float xv = xr[d];
        sa += xv * u[d];
        sb += xv * w[d];
    }
    __shared__ float r1[256], r2[256];
    r1[tid] = sa; r2[tid] = sb;
    __syncthreads();
    for (int s = 128; s; s >>= 1) {
        if (tid < s) { r1[tid] += r1[tid + s]; r2[tid] += r2[tid + s]; }
        __syncthreads();
    }
    if (tid == 0) { av[i] = r1[0]; bv[i] = r2[0]; }
}

__global__ void __launch_bounds__(256) softmax2048_kernel(
    float* __restrict__ p, __half* __restrict__ phi)
{
    const long long roff = (long long)blockIdx.x * 2048;
    float* row = p + roff;
    const int tid = threadIdx.x;

    float4 v0 = ((const float4*)row)[tid];
    float4 v1 = ((const float4*)row)[tid + 256];

    float m = fmaxf(fmaxf(fmaxf(v0.x, v0.y), fmaxf(v0.z, v0.w)),
                    fmaxf(fmaxf(v1.x, v1.y), fmaxf(v1.z, v1.w)));
    __shared__ float red[8];
#pragma unroll
    for (int o = 16; o; o >>= 1) m = fmaxf(m, __shfl_xor_sync(0xffffffffu, m, o));
    if ((tid & 31) == 0) red[tid >> 5] = m;
    __syncthreads();
    m = red[0];
#pragma unroll
    for (int i = 1; i < 8; i++) m = fmaxf(m, red[i]);
    __syncthreads();

    v0.x = expf(v0.x - m); v0.y = expf(v0.y - m);
    v0.z = expf(v0.z - m); v0.w = expf(v0.w - m);
    v1.x = expf(v1.x - m); v1.y = expf(v1.y - m);
    v1.z = expf(v1.z - m); v1.w = expf(v1.w - m);

    float s = (v0.x + v0.y) + (v0.z + v0.w) + (v1.x + v1.y) + (v1.z + v1.w);
#pragma unroll
    for (int o = 16; o; o >>= 1) s += __shfl_xor_sync(0xffffffffu, s, o);
    if ((tid & 31) == 0) red[tid >> 5] = s;
    __syncthreads();
    s = ((red[0] + red[1]) + (red[2] + red[3])) +
        ((red[4] + red[5]) + (red[6] + red[7]));
    float inv = 1.0f / s;

    v0.x *= inv; v0.y *= inv; v0.z *= inv; v0.w *= inv;
    v1.x *= inv; v1.y *= inv; v1.z *= inv; v1.w *= inv;

    ((float4*)row)[tid] = v0;
    ((float4*)row)[tid + 256] = v1;

    const float vv[8] = {v0.x, v0.y, v0.z, v0.w, v1.x, v1.y, v1.z, v1.w};
    const long long off[2] = {roff + (long long)tid * 4,
                              roff + (long long)(tid + 256) * 4};
#pragma unroll
    for (int hseg = 0; hseg < 2; hseg++) {
#pragma unroll
        for (int g = 0; g < 2; g++) {
            __half2 th;
            th.x = __float2half_rn(vv[hseg * 4 + g * 2]);
            th.y = __float2half_rn(vv[hseg * 4 + g * 2 + 1]);
            *(__half2*)(phi + off[hseg] + g * 2) = th;
        }
    }
}

// ============================================================================
// host launcher
// ============================================================================
extern "C" void kernel_launch(void* const* d_in, const int* in_sizes, int n_in,
                              void* d_out, int out_size)
{
    const float* x  = (const float*)d_in[0];
    const float* wq = (const float*)d_in[1];
    const float* bq = (const float*)d_in[2];
    const float* wk = (const float*)d_in[3];
    const float* bk = (const float*)d_in[4];
    const float* wv = (const float*)d_in[5];
    const float* bv = (const float*)d_in[6];
    const float* wp = (const float*)d_in[7];
    const float* bp = (const float*)d_in[8];
    float* out = (float*)d_out;

#define SYM(p, s) void* p##_; cudaGetSymbolAddress(&p##_, s);
    SYM(xhi, g_xhi) SYM(xlo, g_xlo)
    SYM(wqsh, g_wqsh) SYM(wqsl, g_wqsl)
    SYM(wksh, g_wksh) SYM(wksl, g_wksl)
    SYM(wvth, g_wvTh) SYM(wvtl, g_wvTl)
    SYM(wpth, g_wpTh) SYM(wptl, g_wpTl)
    SYM(mtp, g_mtpart)
    SYM(mth, g_mth) SYM(mtl, g_mtl)
    SYM(thi, g_thi) SYM(tlo, g_tlo)
    SYM(vth, g_vThi)
    SYM(phi, g_phi)
    SYM(cxh, g_ctxhi)
    SYM(uu, g_u) SYM(ww, g_w) SYM(cc, g_c)
    SYM(avv, g_av) SYM(bvv, g_bv)
    SYM(sfb, g_scores_fb)
#undef SYM
#define HF(p) ((__half*)p##_)

    float* pattn = (out_size >= (long long)(OUT_ELEMS + PATTN_ELEMS))
                       ? (out + OUT_ELEMS) : (float*)sfb_;

    static int nPersist = 0;
    static cudaStream_t s1 = nullptr;
    static cudaEvent_t evFork = nullptr, evX = nullptr, evJoin = nullptr;
    if (nPersist == 0) {
        int nsm = 148;
        cudaDeviceGetAttribute(&nsm, cudaDevAttrMultiProcessorCount, 0);
        nPersist = 2 * nsm;
        cudaStreamCreateWithFlags(&s1, cudaStreamNonBlocking);
        cudaEventCreateWithFlags(&evFork, cudaEventDisableTiming);
        cudaEventCreateWithFlags(&evX, cudaEventDisableTiming);
        cudaEventCreateWithFlags(&evJoin, cudaEventDisableTiming);

        cudaFuncSetAttribute(v_gemm_p, cudaFuncAttributeMaxDynamicSharedMemorySize, SMEM_2T);
        cudaFuncSetAttribute(mma_gemm_p<2, true,  true,  true,  false, false, false>, cudaFuncAttributeMaxDynamicSharedMemorySize, SMEM_3T);
        cudaFuncSetAttribute(mma_gemm_p<2, true,  true,  false, false, true,  false>, cudaFuncAttributeMaxDynamicSharedMemorySize, SMEM_3T);
        cudaFuncSetAttribute(mma_gemm_p<2, true,  true,  true,  false, false, true >, cudaFuncAttributeMaxDynamicSharedMemorySize, SMEM_3T);
        cudaFuncSetAttribute(mma_gemm_p<4, false, false, false, false, false, false>, cudaFuncAttributeMaxDynamicSharedMemorySize, SMEM_1T);
        cudaFuncSetAttribute(mma_gemm_p<3, false, true,  true,  true,  false, false>, cudaFuncAttributeMaxDynamicSharedMemorySize, SMEM_2T);
    }
    cudaStream_t s0 = 0;

    // ---- fork ----
    cudaEventRecord(evFork, s0);
    cudaStreamWaitEvent(s1, evFork, 0);

    // ---- s1: x split first (t and v need it), then aux, then v ----
    convert_split_kernel<<<(TOK * DIM / 4 + 255) / 256, 256, 0, s1>>>(
        x, HF(xhi), HF(xlo), TOK * DIM / 4);
    cudaEventRecord(evX, s1);
    dim3 gW(DIM / 32, DIM / 32, 1);
    transpose_split_kernel<<<gW, 256, 0, s1>>>(wv, HF(wvth), HF(wvtl), DIM, DIM);
    transpose_split_kernel<<<gW, 256, 0, s1>>>(wp, HF(wpth), HF(wptl), DIM, DIM);
    uvw_kernel<<<DIM, 256, 0, s1>>>(wq, wk, bq, bk, (float*)uu_, (float*)ww_, (float*)cc_);
    av_kernel<<<TOK, 256, 0, s1>>>(x, (float*)uu_, (float*)ww_, (float*)avv_, (float*)bvv_);
    v_gemm_p<<<nPersist, 128, SMEM_2T, s1>>>(
        HF(xhi), HF(wvth), HF(wvtl), bv, HF(vth), DIM / 128, TOK / 128);
    cudaEventRecord(evJoin, s1);

    // ---- s0: critical chain (wq/wk splits -> MT split-K -> reduce -> t) ----
    convert_split_kernel<<<(DIM * DIM / 4 + 255) / 256, 256, 0, s0>>>(
        wq, HF(wqsh), HF(wqsl), DIM * DIM / 4);
    convert_split_kernel<<<(DIM * DIM / 4 + 255) / 256, 256, 0, s0>>>(
        wk, HF(wksh), HF(wksl), DIM * DIM / 4);

    // MT partials: 4 K-chunks x (8x8 tiles) = 256 tiles, fp32 out
    mma_gemm_p<2, true, true, true, false, false, false><<<nPersist, 128, SMEM_3T, s0>>>(
        HF(wksh), HF(wksl), HF(wqsh), HF(wqsl), nullptr,
        (float*)mtp_, nullptr, nullptr, DIM, DIM, /*Kit=*/DIM / 4, 1.f,
        /*sA=*/DIM / 4, /*sB=*/DIM / 4, /*sC=*/(long long)DIM * DIM,
        DIM / 128, DIM / 128, 4, nullptr, nullptr, nullptr);
    // reduce partials -> hi/lo split
    mt_reduce_kernel<<<(DIM * DIM / 4 + 255) / 256, 256, 0, s0>>>(
        (const float*)mtp_, HF(mth), HF(mtl));

    cudaStreamWaitEvent(s0, evX, 0);   // t needs xhi/xlo
    // t = x @ MT^T (3-term, hi/lo out; 512 tiles)
    mma_gemm_p<2, true, true, false, false, true, false><<<nPersist, 128, SMEM_3T, s0>>>(
        HF(xhi), HF(xlo), HF(mth), HF(mtl), nullptr,
        nullptr, HF(thi), HF(tlo), DIM, DIM, DIM, 1.f, 0, 0, 0,
        DIM / 128, TOK / 128, 1, nullptr, nullptr, nullptr);

    // ---- join, then tail on s0 ----
    cudaStreamWaitEvent(s0, evJoin, 0);

    // scores = 32*(t @ x^T + a_i + b_j + c) per batch
    mma_gemm_p<2, true, true, true, false, false, true><<<nPersist, 128, SMEM_3T, s0>>>(
        HF(thi), HF(tlo), HF(xhi), HF(xlo), nullptr, pattn, nullptr, nullptr,
        SEQ, DIM, DIM, 32.f,
        (long long)SEQ * DIM, (long long)SEQ * DIM, (long long)SEQ * SEQ,
        SEQ / 128, SEQ / 128, BATCH,
        (const float*)avv_, (const float*)bvv_, (const float*)cc_);

    softmax2048_kernel<<<TOK, 256, 0, s0>>>(pattn, HF(phi));

    // ctx = p_hi @ v_hi (1-term, 4-stage)
    mma_gemm_p<4, false, false, false, false, false, false><<<nPersist, 128, SMEM_1T, s0>>>(
        HF(phi), nullptr, HF(vth), nullptr, nullptr, nullptr, HF(cxh), nullptr,
        DIM, SEQ, SEQ, 1.f,
        (long long)SEQ * SEQ, (long long)DIM * SEQ, (long long)SEQ * DIM,
        DIM / 128, SEQ / 128, BATCH, nullptr, nullptr, nullptr);

    // out = ctx_hi @ (wp_hi + wp_lo) + bp (2-term, 3-stage)
    mma_gemm_p<3, false, true, true, true, false, false><<<nPersist, 128, SMEM_2T, s0>>>(
        HF(cxh), nullptr, HF(wpth), HF(wptl), bp, out, nullptr, nullptr,
        DIM, DIM, DIM, 1.f, 0, 0, 0,
        DIM / 128, TOK / 128, 1, nullptr, nullptr, nullptr);
}

// round 13
// speedup vs baseline: 1.2926x; 1.0238x over previous
#include <cuda_runtime.h>
#include <cuda_fp16.h>
#include <cstdint>

// ============================================================================
// Fused attention block via mma.sync (HMMA), fp16 hi/lo split arithmetic.
// Algebraic rewrite: scores = 32*( x(WqWk^T)x^T + a_i + b_j + c ).
// R13: dependency-exact stream join — scores waits only on {t, av/bv};
// v-projection overlaps the scores GEMM and joins at ctx.
// Terms: 3-term (MT, t, scores), 2-term (v/out proj), 1-term (ctx).
// 128x128 tiles, 128 thr/4 warps, 64x64 warp tiles, 2 CTA/SM.
// ============================================================================

#define TOK 8192
#define DIM 1024
#define SEQ 2048
#define BATCH 4

static const long long OUT_ELEMS = (long long)TOK * DIM;
static const long long PATTN_ELEMS = (long long)BATCH * SEQ * SEQ;

// ---------------- device scratch ----------------
__device__ __half g_xhi[TOK * DIM], g_xlo[TOK * DIM];
__device__ __half g_wqsh[DIM * DIM], g_wqsl[DIM * DIM];
__device__ __half g_wksh[DIM * DIM], g_wksl[DIM * DIM];
__device__ __half g_wvTh[DIM * DIM], g_wvTl[DIM * DIM];
__device__ __half g_wpTh[DIM * DIM], g_wpTl[DIM * DIM];
__device__ float  g_mtpart[4 * DIM * DIM];                // split-K partials
__device__ __half g_mth[DIM * DIM], g_mtl[DIM * DIM];
__device__ __half g_thi[TOK * DIM], g_tlo[TOK * DIM];
__device__ __half g_vThi[TOK * DIM];
__device__ __half g_phi[BATCH * SEQ * SEQ];
__device__ __half g_ctxhi[TOK * DIM];
__device__ float  g_u[DIM], g_w[DIM], g_c[1];
__device__ float  g_av[TOK], g_bv[TOK];
__device__ float  g_scores_fb[BATCH * SEQ * SEQ];

// ---------------- PTX helpers ----------------
__device__ __forceinline__ uint32_t smem_u32_f(const void* p) {
    uint32_t a;
    asm("{ .reg .u64 t; cvta.to.shared.u64 t, %1; cvt.u32.u64 %0, t; }"
        : "=r"(a) : "l"(p));
    return a;
}
__device__ __forceinline__ void cp16(uint32_t dst, const void* src) {
    asm volatile("cp.async.cg.shared.global [%0], [%1], 16;" :: "r"(dst), "l"(src));
}
__device__ __forceinline__ void cp_commit() { asm volatile("cp.async.commit_group;"); }
template <int N>
__device__ __forceinline__ void cp_wait() {
    asm volatile("cp.async.wait_group %0;" :: "n"(N));
}
__device__ __forceinline__ void ldm_x4(uint32_t r[4], uint32_t addr) {
    asm volatile("ldmatrix.sync.aligned.m8n8.x4.shared.b16 {%0,%1,%2,%3}, [%4];"
                 : "=r"(r[0]), "=r"(r[1]), "=r"(r[2]), "=r"(r[3]) : "r"(addr));
}
__device__ __forceinline__ void mma16816(float c[4], const uint32_t a[4],
                                         const uint32_t b0, const uint32_t b1) {
    asm volatile(
        "mma.sync.aligned.m16n8k16.row.col.f32.f16.f16.f32 "
        "{%0,%1,%2,%3},{%4,%5,%6,%7},{%8,%9},{%0,%1,%2,%3};"
        : "+f"(c[0]), "+f"(c[1]), "+f"(c[2]), "+f"(c[3])
        : "r"(a[0]), "r"(a[1]), "r"(a[2]), "r"(a[3]), "r"(b0), "r"(b1));
}

#define PITCH 80u
#define TILE_B (128u * PITCH)            // 10240 B

// ============================================================================
// GEMM core for one 128x128 output tile.
// Kld = row stride of A/B; Kit = K extent actually iterated (split-K).
// ============================================================================
template <int NS, bool ASPLIT, bool BSPLIT, bool WF32, bool HASBIAS, bool WLO,
          bool WTRANS, bool SCB>
__device__ __forceinline__ void gemm_core(
    const __half* __restrict__ Ah, const __half* __restrict__ Al,
    const __half* __restrict__ Bh, const __half* __restrict__ Bl,
    const float* __restrict__ bias,
    float* __restrict__ Cf, __half* __restrict__ Chi, __half* __restrict__ Clo,
    int N, int Kld, int Kit, float alpha, int row0, int col0, long long cOff,
    const float* __restrict__ av, const float* __restrict__ bv,
    const float* __restrict__ cb)
{
    constexpr uint32_t OF_AH = 0u;
    constexpr uint32_t OF_BH = TILE_B;
    constexpr uint32_t OF_AL = 2u * TILE_B;
    constexpr uint32_t OF_BL = (ASPLIT ? 3u : 2u) * TILE_B;
    constexpr uint32_t STG_SZ = (2u + (ASPLIT ? 1u : 0u) + (BSPLIT ? 1u : 0u)) * TILE_B;

    extern __shared__ char smem_raw[];
    const uint32_t base = smem_u32_f(smem_raw);
    const int tid = threadIdx.x;
    const int warp = tid >> 5, lane = tid & 31;

    long long aOff[4], bOff[4];
    uint32_t dOff[4];
#pragma unroll
    for (int j = 0; j < 4; j++) {
        int c = tid + j * 128;
        int r = c >> 2, q = c & 3;
        aOff[j] = (long long)(row0 + r) * Kld + q * 8;
        bOff[j] = (long long)(col0 + r) * Kld + q * 8;
        dOff[j] = (uint32_t)r * PITCH + (uint32_t)q * 16u;
    }

    const int m0 = (warp & 1) * 64, n0 = (warp >> 1) * 64;
    const uint32_t aLane = (uint32_t)(lane & 15) * PITCH + (uint32_t)(lane >> 4) * 16u;
    const uint32_t bLane = (uint32_t)((lane & 7) + ((lane >> 4) << 3)) * PITCH +
                           (uint32_t)((lane >> 3) & 1) * 16u;

    float acc[4][8][4];
#pragma unroll
    for (int i = 0; i < 4; i++)
#pragma unroll
        for (int j = 0; j < 8; j++)
#pragma unroll
            for (int e = 0; e < 4; e++) acc[i][j][e] = 0.f;

    const int nk = Kit >> 5;

#pragma unroll
    for (int s = 0; s < NS - 1; s++) {
        uint32_t sb = base + (uint32_t)s * STG_SZ;
        long long k0 = (long long)s * 32;
#pragma unroll
        for (int j = 0; j < 4; j++) {
            cp16(sb + OF_AH + dOff[j], Ah + aOff[j] + k0);
            if (ASPLIT) cp16(sb + OF_AL + dOff[j], Al + aOff[j] + k0);
            cp16(sb + OF_BH + dOff[j], Bh + bOff[j] + k0);
            if (BSPLIT) cp16(sb + OF_BL + dOff[j], Bl + bOff[j] + k0);
        }
        cp_commit();
    }

    for (int i = 0; i < nk; i++) {
        const int pend = (nk - 1 - i < NS - 2) ? (nk - 1 - i) : (NS - 2);
        if (pend >= 2)      cp_wait<2>();
        else if (pend == 1) cp_wait<1>();
        else                cp_wait<0>();
        __syncthreads();

        if (i + NS - 1 < nk) {
            const int s = (i + NS - 1) % NS;
            uint32_t sb = base + (uint32_t)s * STG_SZ;
            long long k0 = (long long)(i + NS - 1) * 32;
#pragma unroll
            for (int j = 0; j < 4; j++) {
                cp16(sb + OF_AH + dOff[j], Ah + aOff[j] + k0);
                if (ASPLIT) cp16(sb + OF_AL + dOff[j], Al + aOff[j] + k0);
                cp16(sb + OF_BH + dOff[j], Bh + bOff[j] + k0);
                if (BSPLIT) cp16(sb + OF_BL + dOff[j], Bl + bOff[j] + k0);
            }
            cp_commit();
        }

        const uint32_t sb = base + (uint32_t)(i % NS) * STG_SZ;
#pragma unroll
        for (int ks = 0; ks < 2; ks++) {
            const uint32_t kb = (uint32_t)ks * 32u;
            uint32_t ah[4][4], al[4][4], bh[4][4], bl[4][4];
#pragma unroll
            for (int mf = 0; mf < 4; mf++) {
                uint32_t ro = (uint32_t)(m0 + mf * 16) * PITCH + kb + aLane;
                ldm_x4(ah[mf], sb + OF_AH + ro);
                if (ASPLIT) ldm_x4(al[mf], sb + OF_AL + ro);
            }
#pragma unroll
            for (int q = 0; q < 4; q++) {
                uint32_t ro = (uint32_t)(n0 + q * 16) * PITCH + kb + bLane;
                ldm_x4(bh[q], sb + OF_BH + ro);
                if (BSPLIT) ldm_x4(bl[q], sb + OF_BL + ro);
            }
#pragma unroll
            for (int mf = 0; mf < 4; mf++)
#pragma unroll
                for (int nf = 0; nf < 8; nf++) {
                    const int q = nf >> 1, h = (nf & 1) * 2;
                    mma16816(acc[mf][nf], ah[mf], bh[q][h], bh[q][h + 1]);
                    if (ASPLIT) mma16816(acc[mf][nf], al[mf], bh[q][h], bh[q][h + 1]);
                    if (BSPLIT) mma16816(acc[mf][nf], ah[mf], bl[q][h], bl[q][h + 1]);
                }
        }
    }

    // ---- epilogue ----
    const int tg = lane >> 2, tl = lane & 3;
    const float c0 = SCB ? __ldg(cb) : 0.f;
#pragma unroll
    for (int mf = 0; mf < 4; mf++) {
#pragma unroll
        for (int nf = 0; nf < 8; nf++) {
            const int col = col0 + n0 + nf * 8 + tl * 2;
            float b0 = 0.f, b1 = 0.f;
            if (HASBIAS) { b0 = __ldg(bias + col); b1 = __ldg(bias + col + 1); }
            float bc0 = 0.f, bc1 = 0.f;
            if (SCB) { bc0 = __ldg(bv + col) + c0; bc1 = __ldg(bv + col + 1) + c0; }
#pragma unroll
            for (int hrow = 0; hrow < 2; hrow++) {
                const int row = row0 + m0 + mf * 16 + tg + hrow * 8;
                float v0, v1;
                if (SCB) {
                    const float ar = __ldg(av + row);
                    v0 = (acc[mf][nf][hrow * 2 + 0] + ar + bc0) * alpha;
                    v1 = (acc[mf][nf][hrow * 2 + 1] + ar + bc1) * alpha;
                } else {
                    v0 = acc[mf][nf][hrow * 2 + 0] * alpha + b0;
                    v1 = acc[mf][nf][hrow * 2 + 1] * alpha + b1;
                }
                if (WTRANS) {
                    Chi[cOff + (long long)col * SEQ + row] = __float2half_rn(v0);
                    Chi[cOff + (long long)(col + 1) * SEQ + row] = __float2half_rn(v1);
                } else {
                    const long long off = cOff + (long long)row * N + col;
                    if (WF32) {
                        float2 o; o.x = v0; o.y = v1;
                        *(float2*)(Cf + off) = o;
                    } else {
                        __half h0 = __float2half_rn(v0);
                        __half h1 = __float2half_rn(v1);
                        __half2 th; th.x = h0; th.y = h1;
                        *(__half2*)(Chi + off) = th;
                        if (WLO) {
                            __half2 tlh;
                            tlh.x = __float2half_rn(v0 - __half2float(h0));
                            tlh.y = __float2half_rn(v1 - __half2float(h1));
                            *(__half2*)(Clo + off) = tlh;
                        }
                    }
                }
            }
        }
    }
}

// ---------------- persistent GEMM over (ntz, nty, ntx) tiles ----------------
template <int NS, bool ASPLIT, bool BSPLIT, bool WF32, bool HASBIAS, bool WLO,
          bool SCB>
__global__ void __launch_bounds__(128) mma_gemm_p(
    const __half* __restrict__ Ah_g, const __half* __restrict__ Al_g,
    const __half* __restrict__ Bh_g, const __half* __restrict__ Bl_g,
    const float* __restrict__ bias,
    float* __restrict__ Cf, __half* __restrict__ Chi, __half* __restrict__ Clo,
    int N, int Kld, int Kit, float alpha,
    long long sA, long long sB, long long sC,
    int ntx, int nty, int ntz,
    const float* __restrict__ av, const float* __restrict__ bv,
    const float* __restrict__ cb)
{
    const int total = ntx * nty * ntz;
    const int nxy = ntx * nty;
    for (int t = blockIdx.x; t < total; t += gridDim.x) {
        const int tz = t / nxy;
        const int r = t - tz * nxy;
        const int ty = r / ntx;
        const int tx = r - ty * ntx;
        __syncthreads();
        gemm_core<NS, ASPLIT, BSPLIT, WF32, HASBIAS, WLO, false, SCB>(
            Ah_g + (long long)tz * sA, ASPLIT ? (Al_g + (long long)tz * sA) : nullptr,
            Bh_g + (long long)tz * sB, BSPLIT ? (Bl_g + (long long)tz * sB) : nullptr,
            bias, Cf, Chi, Clo, N, Kld, Kit, alpha,
            ty * 128, tx * 128, (long long)tz * sC,
            SCB ? (av + (long long)tz * SEQ) : nullptr,
            SCB ? (bv + (long long)tz * SEQ) : nullptr, cb);
    }
}

// persistent v projection: v = x @ Wv (2-term, 3-stage, transposed out -> vT)
__global__ void __launch_bounds__(128) v_gemm_p(
    const __half* __restrict__ xhi,
    const __half* __restrict__ wvTh, const __half* __restrict__ wvTl,
    const float* __restrict__ bvb,
    __half* __restrict__ vThi,
    int ntx, int nty)
{
    const int total = ntx * nty;
    for (int t = blockIdx.x; t < total; t += gridDim.x) {
        const int ty = t / ntx;
        const int tx = t - ty * ntx;
        __syncthreads();
        const long long batch = (long long)((ty * 128) >> 11);
        gemm_core<3, false, true, false, true, false, true, false>(
            xhi, nullptr, wvTh, wvTl, bvb,
            nullptr, vThi, nullptr, DIM, DIM, DIM, 1.f,
            ty * 128, tx * 128, batch * SEQ * (DIM - 1),
            nullptr, nullptr, nullptr);
    }
}

// smem budgets
#define SMEM_3T  (2 * 4 * 10240)        // 81920
#define SMEM_2T  (3 * 3 * 10240)        // 92160
#define SMEM_1T  (4 * 2 * 10240)        // 81920

// ============================================================================
// helper kernels
// ============================================================================
__global__ void __launch_bounds__(256) convert_split_kernel(
    const float* __restrict__ in, __half* __restrict__ hi,
    __half* __restrict__ lo, long long n4)
{
    long long i = (long long)blockIdx.x * 256 + threadIdx.x;
    if (i >= n4) return;
    float4 v = ((const float4*)in)[i];
    __half h0 = __float2half_rn(v.x), h1 = __float2half_rn(v.y);
    __half h2 = __float2half_rn(v.z), h3 = __float2half_rn(v.w);
    __half2 a, b; a.x = h0; a.y = h1; b.x = h2; b.y = h3;
    ((__half2*)hi)[i * 2 + 0] = a;
    ((__half2*)hi)[i * 2 + 1] = b;
    __half2 c, d;
    c.x = __float2half_rn(v.x - __half2float(h0));
    c.y = __float2half_rn(v.y - __half2float(h1));
    d.x = __float2half_rn(v.z - __half2float(h2));
    d.y = __float2half_rn(v.w - __half2float(h3));
    ((__half2*)lo)[i * 2 + 0] = c;
    ((__half2*)lo)[i * 2 + 1] = d;
}

// reduce 4 fp32 split-K partials -> hi/lo fp16 splits
__global__ void __launch_bounds__(256) mt_reduce_kernel(
    const float* __restrict__ part, __half* __restrict__ hi,
    __half* __restrict__ lo)
{
    const long long n4 = (long long)DIM * DIM / 4;
    long long i = (long long)blockIdx.x * 256 + threadIdx.x;
    if (i >= n4) return;
    const long long stride4 = n4;
    float4 a = ((const float4*)part)[i];
    float4 b = ((const float4*)part)[i + stride4];
    float4 c = ((const float4*)part)[i + 2 * stride4];
    float4 d = ((const float4*)part)[i + 3 * stride4];
    float4 s;
    s.x = (a.x + b.x) + (c.x + d.x);
    s.y = (a.y + b.y) + (c.y + d.y);
    s.z = (a.z + b.z) + (c.z + d.z);
    s.w = (a.w + b.w) + (c.w + d.w);
    __half h0 = __float2half_rn(s.x), h1 = __float2half_rn(s.y);
    __half h2 = __float2half_rn(s.z), h3 = __float2half_rn(s.w);
    __half2 p, q; p.x = h0; p.y = h1; q.x = h2; q.y = h3;
    ((__half2*)hi)[i * 2 + 0] = p;
    ((__half2*)hi)[i * 2 + 1] = q;
    __half2 r, t;
    r.x = __float2half_rn(s.x - __half2float(h0));
    r.y = __float2half_rn(s.y - __half2float(h1));
    t.x = __float2half_rn(s.z - __half2float(h2));
    t.y = __float2half_rn(s.w - __half2float(h3));
    ((__half2*)lo)[i * 2 + 0] = r;
    ((__half2*)lo)[i * 2 + 1] = t;
}

__global__ void __launch_bounds__(256) transpose_split_kernel(
    const float* __restrict__ in, __half* __restrict__ hi,
    __half* __restrict__ lo, int R, int C)
{
    __shared__ float t[32][33];
    const int c0 = blockIdx.x * 32, r0 = blockIdx.y * 32;
    const int tx = threadIdx.x & 31, ty = threadIdx.x >> 5;
#pragma unroll
    for (int j = 0; j < 4; j++)
        t[ty + j * 8][tx] = in[(long long)(r0 + ty + j * 8) * C + c0 + tx];
    __syncthreads();
#pragma unroll
    for (int j = 0; j < 4; j++) {
        int oc = c0 + ty + j * 8;
        float v = t[tx][ty + j * 8];
        long long o = (long long)oc * R + r0 + tx;
        __half h = __float2half_rn(v);
        hi[o] = h;
        lo[o] = __float2half_rn(v - __half2float(h));
    }
}

// u = Wq*bk, w = Wk*bq (two rows per block, float4 loads), c = bq.bk
__global__ void __launch_bounds__(256) uvw_kernel(
    const float* __restrict__ wq, const float* __restrict__ wk,
    const float* __restrict__ bq, const float* __restrict__ bk,
    float* __restrict__ u, float* __restrict__ w, float* __restrict__ cb)
{
    const int d = blockIdx.x * 2 + (threadIdx.x >> 7);  // 2 rows per block
    const int tid = threadIdx.x & 127;
    float su = 0.f, sw = 0.f;
    const float4* wq4 = (const float4*)(wq + (long long)d * DIM);
    const float4* wk4 = (const float4*)(wk + (long long)d * DIM);
    const float4* bk4 = (const float4*)bk;
    const float4* bq4 = (const float4*)bq;
    for (int f = tid; f < DIM / 4; f += 128) {
        float4 a = wq4[f], b = bk4[f];
        su += a.x * b.x + a.y * b.y + a.z * b.z + a.w * b.w;
        float4 c = wk4[f], e = bq4[f];
        sw += c.x * e.x + c.y * e.y + c.z * e.z + c.w * e.w;
    }
#pragma unroll
    for (int o = 16; o; o >>= 1) {
        su += __shfl_xor_sync(0xffffffffu, su, o);
        sw += __shfl_xor_sync(0xffffffffu, sw, o);
    }
    __shared__ float r1[2][4], r2[2][4];
    const int half = threadIdx.x >> 7, wrp = (threadIdx.x >> 5) & 3;
    if ((tid & 31) == 0) { r1[half][wrp] = su; r2[half][wrp] = sw; }
    __syncthreads();
    if (tid == 0) {
        u[d] = (r1[half][0] + r1[half][1]) + (r1[half][2] + r1[half][3]);
        w[d] = (r2[half][0] + r2[half][1]) + (r2[half][2] + r2[half][3]);
    }
    if (d == 0 && tid == 0) {
        float c = 0.f;
        for (int f = 0; f < DIM; f++) c += bq[f] * bk[f];
        cb[0] = c;
    }
}

__global__ void __launch_bounds__(256) av_kernel(
    const float* __restrict__ x, const float* __restrict__ u,
    const float* __restrict__ w, float* __restrict__ av, float* __restrict__ bv)
{
    const long long i = blockIdx.x;
    const float* xr = x + i * DIM;
    const int tid = threadIdx.x;
    float sa = 0.f, sb = 0.f;
    for (int d = tid; d < DIM; d += 256) {
        float xv = xr[d];
        sa += xv * u[d];
        sb += xv * w[d];
    }
    __shared__ float r1[256], r2[256];
    r1[tid] = sa; r2[tid] = sb;
    __syncthreads();
    for (int s = 128; s; s >>= 1) {
        if (tid < s) { r1[tid] += r1[tid + s]; r2[tid] += r2[tid + s]; }
        __syncthreads();
    }
    if (tid == 0) { av[i] = r1[0]; bv[i] = r2[0]; }
}

__global__ void __launch_bounds__(256) softmax2048_kernel(
    float* __restrict__ p, __half* __restrict__ phi)
{
    const long long roff = (long long)blockIdx.x * 2048;
    float* row = p + roff;
    const int tid = threadIdx.x;

    float4 v0 = ((const float4*)row)[tid];
    float4 v1 = ((const float4*)row)[tid + 256];

    float m = fmaxf(fmaxf(fmaxf(v0.x, v0.y), fmaxf(v0.z, v0.w)),
                    fmaxf(fmaxf(v1.x, v1.y), fmaxf(v1.z, v1.w)));
    __shared__ float red[8];
#pragma unroll
    for (int o = 16; o; o >>= 1) m = fmaxf(m, __shfl_xor_sync(0xffffffffu, m, o));
    if ((tid & 31) == 0) red[tid >> 5] = m;
    __syncthreads();
    m = red[0];
#pragma unroll
    for (int i = 1; i < 8; i++) m = fmaxf(m, red[i]);
    __syncthreads();

    v0.x = expf(v0.x - m); v0.y = expf(v0.y - m);
    v0.z = expf(v0.z - m); v0.w = expf(v0.w - m);
    v1.x = expf(v1.x - m); v1.y = expf(v1.y - m);
    v1.z = expf(v1.z - m); v1.w = expf(v1.w - m);

    float s = (v0.x + v0.y) + (v0.z + v0.w) + (v1.x + v1.y) + (v1.z + v1.w);
#pragma unroll
    for (int o = 16; o; o >>= 1) s += __shfl_xor_sync(0xffffffffu, s, o);
    if ((tid & 31) == 0) red[tid >> 5] = s;
    __syncthreads();
    s = ((red[0] + red[1]) + (red[2] + red[3])) +
        ((red[4] + red[5]) + (red[6] + red[7]));
    float inv = 1.0f / s;

    v0.x *= inv; v0.y *= inv; v0.z *= inv; v0.w *= inv;
    v1.x *= inv; v1.y *= inv; v1.z *= inv; v1.w *= inv;

    ((float4*)row)[tid] = v0;
    ((float4*)row)[tid + 256] = v1;

    const float vv[8] = {v0.x, v0.y, v0.z, v0.w, v1.x, v1.y, v1.z, v1.w};
    const long long off[2] = {roff + (long long)tid * 4,
                              roff + (long long)(tid + 256) * 4};
#pragma unroll
    for (int hseg = 0; hseg < 2; hseg++) {
#pragma unroll
        for (int g = 0; g < 2; g++) {
            __half2 th;
            th.x = __float2half_rn(vv[hseg * 4 + g * 2]);
            th.y = __float2half_rn(vv[hseg * 4 + g * 2 + 1]);
            *(__half2*)(phi + off[hseg] + g * 2) = th;
        }
    }
}

// ============================================================================
// host launcher
// ============================================================================
extern "C" void kernel_launch(void* const* d_in, const int* in_sizes, int n_in,
                              void* d_out, int out_size)
{
    const float* x  = (const float*)d_in[0];
    const float* wq = (const float*)d_in[1];
    const float* bq = (const float*)d_in[2];
    const float* wk = (const float*)d_in[3];
    const float* bk = (const float*)d_in[4];
    const float* wv = (const float*)d_in[5];
    const float* bv = (const float*)d_in[6];
    const float* wp = (const float*)d_in[7];
    const float* bp = (const float*)d_in[8];
    float* out = (float*)d_out;

#define SYM(p, s) void* p##_; cudaGetSymbolAddress(&p##_, s);
    SYM(xhi, g_xhi) SYM(xlo, g_xlo)
    SYM(wqsh, g_wqsh) SYM(wqsl, g_wqsl)
    SYM(wksh, g_wksh) SYM(wksl, g_wksl)
    SYM(wvth, g_wvTh) SYM(wvtl, g_wvTl)
    SYM(wpth, g_wpTh) SYM(wptl, g_wpTl)
    SYM(mtp, g_mtpart)
    SYM(mth, g_mth) SYM(mtl, g_mtl)
    SYM(thi, g_thi) SYM(tlo, g_tlo)
    SYM(vth, g_vThi)
    SYM(phi, g_phi)
    SYM(cxh, g_ctxhi)
    SYM(uu, g_u) SYM(ww, g_w) SYM(cc, g_c)
    SYM(avv, g_av) SYM(bvv, g_bv)
    SYM(sfb, g_scores_fb)
#undef SYM
#define HF(p) ((__half*)p##_)

    float* pattn = (out_size >= (long long)(OUT_ELEMS + PATTN_ELEMS))
                       ? (out + OUT_ELEMS) : (float*)sfb_;

    static int nPersist = 0;
    static cudaStream_t s1 = nullptr;
    static cudaEvent_t evFork = nullptr, evX = nullptr, evAux = nullptr,
                       evJoin = nullptr;
    if (nPersist == 0) {
        int nsm = 148;
        cudaDeviceGetAttribute(&nsm, cudaDevAttrMultiProcessorCount, 0);
        nPersist = 2 * nsm;
        cudaStreamCreateWithFlags(&s1, cudaStreamNonBlocking);
        cudaEventCreateWithFlags(&evFork, cudaEventDisableTiming);
        cudaEventCreateWithFlags(&evX, cudaEventDisableTiming);
        cudaEventCreateWithFlags(&evAux, cudaEventDisableTiming);
        cudaEventCreateWithFlags(&evJoin, cudaEventDisableTiming);

        cudaFuncSetAttribute(v_gemm_p, cudaFuncAttributeMaxDynamicSharedMemorySize, SMEM_2T);
        cudaFuncSetAttribute(mma_gemm_p<2, true,  true,  true,  false, false, false>, cudaFuncAttributeMaxDynamicSharedMemorySize, SMEM_3T);
        cudaFuncSetAttribute(mma_gemm_p<2, true,  true,  false, false, true,  false>, cudaFuncAttributeMaxDynamicSharedMemorySize, SMEM_3T);
        cudaFuncSetAttribute(mma_gemm_p<2, true,  true,  true,  false, false, true >, cudaFuncAttributeMaxDynamicSharedMemorySize, SMEM_3T);
        cudaFuncSetAttribute(mma_gemm_p<4, false, false, false, false, false, false>, cudaFuncAttributeMaxDynamicSharedMemorySize, SMEM_1T);
        cudaFuncSetAttribute(mma_gemm_p<3, false, true,  true,  true,  false, false>, cudaFuncAttributeMaxDynamicSharedMemorySize, SMEM_2T);
    }
    cudaStream_t s0 = 0;

    // ---- fork ----
    cudaEventRecord(evFork, s0);
    cudaStreamWaitEvent(s1, evFork, 0);

    // ---- s1: x split (t and v need it), aux (scores needs), then v ----
    convert_split_kernel<<<(TOK * DIM / 4 + 255) / 256, 256, 0, s1>>>(
        x, HF(xhi), HF(xlo), TOK * DIM / 4);
    cudaEventRecord(evX, s1);
    uvw_kernel<<<DIM / 2, 256, 0, s1>>>(wq, wk, bq, bk,
                                        (float*)uu_, (float*)ww_, (float*)cc_);
    av_kernel<<<TOK, 256, 0, s1>>>(x, (float*)uu_, (float*)ww_, (float*)avv_, (float*)bvv_);
    cudaEventRecord(evAux, s1);   // scores deps (besides t) ready
    dim3 gW(DIM / 32, DIM / 32, 1);
    transpose_split_kernel<<<gW, 256, 0, s1>>>(wv, HF(wvth), HF(wvtl), DIM, DIM);
    transpose_split_kernel<<<gW, 256, 0, s1>>>(wp, HF(wpth), HF(wptl), DIM, DIM);
    v_gemm_p<<<nPersist, 128, SMEM_2T, s1>>>(
        HF(xhi), HF(wvth), HF(wvtl), bv, HF(vth), DIM / 128, TOK / 128);
    cudaEventRecord(evJoin, s1);  // v (and wp transpose) ready

    // ---- s0: critical chain (wq/wk splits -> MT split-K -> reduce -> t) ----
    convert_split_kernel<<<(DIM * DIM / 4 + 255) / 256, 256, 0, s0>>>(
        wq, HF(wqsh), HF(wqsl), DIM * DIM / 4);
    convert_split_kernel<<<(DIM * DIM / 4 + 255) / 256, 256, 0, s0>>>(
        wk, HF(wksh), HF(wksl), DIM * DIM / 4);

    // MT partials: 4 K-chunks x (8x8 tiles) = 256 tiles, fp32 out
    mma_gemm_p<2, true, true, true, false, false, false><<<nPersist, 128, SMEM_3T, s0>>>(
        HF(wksh), HF(wksl), HF(wqsh), HF(wqsl), nullptr,
        (float*)mtp_, nullptr, nullptr, DIM, DIM, /*Kit=*/DIM / 4, 1.f,
        /*sA=*/DIM / 4, /*sB=*/DIM / 4, /*sC=*/(long long)DIM * DIM,
        DIM / 128, DIM / 128, 4, nullptr, nullptr, nullptr);
    mt_reduce_kernel<<<(DIM * DIM / 4 + 255) / 256, 256, 0, s0>>>(
        (const float*)mtp_, HF(mth), HF(mtl));

    cudaStreamWaitEvent(s0, evX, 0);   // t needs xhi/xlo
    mma_gemm_p<2, true, true, false, false, true, false><<<nPersist, 128, SMEM_3T, s0>>>(
        HF(xhi), HF(xlo), HF(mth), HF(mtl), nullptr,
        nullptr, HF(thi), HF(tlo), DIM, DIM, DIM, 1.f, 0, 0, 0,
        DIM / 128, TOK / 128, 1, nullptr, nullptr, nullptr);

    // ---- scores waits only on aux (not on v) ----
    cudaStreamWaitEvent(s0, evAux, 0);
    mma_gemm_p<2, true, true, true, false, false, true><<<nPersist, 128, SMEM_3T, s0>>>(
        HF(thi), HF(tlo), HF(xhi), HF(xlo), nullptr, pattn, nullptr, nullptr,
        SEQ, DIM, DIM, 32.f,
        (long long)SEQ * DIM, (long long)SEQ * DIM, (long long)SEQ * SEQ,
        SEQ / 128, SEQ / 128, BATCH,
        (const float*)avv_, (const float*)bvv_, (const float*)cc_);

    softmax2048_kernel<<<TOK, 256, 0, s0>>>(pattn, HF(phi));

    // ---- ctx is the first consumer of v ----
    cudaStreamWaitEvent(s0, evJoin, 0);
    mma_gemm_p<4, false, false, false, false, false, false><<<nPersist, 128, SMEM_1T, s0>>>(
        HF(phi), nullptr, HF(vth), nullptr, nullptr, nullptr, HF(cxh), nullptr,
        DIM, SEQ, SEQ, 1.f,
        (long long)SEQ * SEQ, (long long)DIM * SEQ, (long long)SEQ * DIM,
        DIM / 128, SEQ / 128, BATCH, nullptr, nullptr, nullptr);

    // out = ctx_hi @ (wp_hi + wp_lo) + bp (2-term, 3-stage)
    mma_gemm_p<3, false, true, true, true, false, false><<<nPersist, 128, SMEM_2T, s0>>>(
        HF(cxh), nullptr, HF(wpth), HF(wptl), bp, out, nullptr, nullptr,
        DIM, DIM, DIM, 1.f, 0, 0, 0,
        DIM / 128, TOK / 128, 1, nullptr, nullptr, nullptr);
}